// round 14
// baseline (speedup 1.0000x reference)
#include <cuda_runtime.h>
#include <cuda_bf16.h>
#include <math.h>
#include <cstdint>

#define S_LEN   2048
#define D_MOD   2048
#define NHEAD   16
#define HD      128
#define BATCH   2
#define M_TOT   (BATCH * S_LEN)   // 4096

// ---------------------------------------------------------------------------
// helpers
// ---------------------------------------------------------------------------
__device__ __forceinline__ uint32_t smem_u32(const void* p) {
    uint32_t a;
    asm("{ .reg .u64 t; cvta.to.shared.u64 t, %1; cvt.u32.u64 %0, t; }"
        : "=r"(a) : "l"(p));
    return a;
}

#define CP_ASYNC16(dst, src) \
    asm volatile("cp.async.cg.shared.global [%0], [%1], 16;" \
                 :: "r"(dst), "l"(src) : "memory")
#define CP_COMMIT() asm volatile("cp.async.commit_group;" ::: "memory")
#define CP_WAIT1()  asm volatile("cp.async.wait_group 1;" ::: "memory")
#define CP_WAIT0()  asm volatile("cp.async.wait_group 0;" ::: "memory")

__device__ __forceinline__ void ldm_x4(uint32_t addr, uint32_t& r0, uint32_t& r1,
                                       uint32_t& r2, uint32_t& r3) {
    asm volatile("ldmatrix.sync.aligned.m8n8.x4.shared.b16 {%0,%1,%2,%3}, [%4];"
                 : "=r"(r0), "=r"(r1), "=r"(r2), "=r"(r3) : "r"(addr));
}
__device__ __forceinline__ void ldm_x4t(uint32_t addr, uint32_t& r0, uint32_t& r1,
                                        uint32_t& r2, uint32_t& r3) {
    asm volatile("ldmatrix.sync.aligned.m8n8.x4.trans.shared.b16 {%0,%1,%2,%3}, [%4];"
                 : "=r"(r0), "=r"(r1), "=r"(r2), "=r"(r3) : "r"(addr));
}
__device__ __forceinline__ void mma_bf16(float* d, const uint32_t* a, const uint32_t* b) {
    asm volatile(
        "mma.sync.aligned.m16n8k16.row.col.f32.bf16.bf16.f32 "
        "{%0,%1,%2,%3}, {%4,%5,%6,%7}, {%8,%9}, {%0,%1,%2,%3};"
        : "+f"(d[0]), "+f"(d[1]), "+f"(d[2]), "+f"(d[3])
        : "r"(a[0]), "r"(a[1]), "r"(a[2]), "r"(a[3]), "r"(b[0]), "r"(b[1]));
}
__device__ __forceinline__ uint32_t bf16x2_pack(float lo, float hi) {
    uint32_t r;
    asm("cvt.rn.bf16x2.f32 %0, %1, %2;" : "=r"(r) : "f"(hi), "f"(lo));
    return r;
}
__device__ __forceinline__ uint32_t split2(float a, float b, uint32_t& lo) {
    uint32_t h = bf16x2_pack(a, b);
    float ha = __uint_as_float(h << 16);
    float hb = __uint_as_float(h & 0xffff0000u);
    lo = bf16x2_pack(a - ha, b - hb);
    return h;
}
__device__ __forceinline__ float ex2f(float x) {
    float y; asm("ex2.approx.ftz.f32 %0, %1;" : "=f"(y) : "f"(x)); return y;
}

// ---------------------------------------------------------------------------
// Scratch (device globals: allocation-free rule)
// ---------------------------------------------------------------------------
__device__ __nv_bfloat16 g_xhi [M_TOT * D_MOD];
__device__ __nv_bfloat16 g_xlo [M_TOT * D_MOD];
__device__ __nv_bfloat16 g_whi [4][D_MOD * D_MOD];
__device__ __nv_bfloat16 g_wlo [4][D_MOD * D_MOD];
__device__ __nv_bfloat16 g_aohi[M_TOT * D_MOD];
__device__ __nv_bfloat16 g_aolo[M_TOT * D_MOD];
__device__ __nv_bfloat16 g_qhi [M_TOT * D_MOD];
__device__ __nv_bfloat16 g_qlo [M_TOT * D_MOD];
__device__ __nv_bfloat16 g_khi [M_TOT * D_MOD];
__device__ __nv_bfloat16 g_klo [M_TOT * D_MOD];
__device__ __nv_bfloat16 g_vhi [M_TOT * D_MOD];
__device__ __nv_bfloat16 g_vlo [M_TOT * D_MOD];

// ---------------------------------------------------------------------------
// Fused split: x (2 regions) + 4 weights (1 region each) -> hi/lo bf16.
// ---------------------------------------------------------------------------
#define REG4 (1024 * 1024)     // float4 per region
__global__ __launch_bounds__(256) void split_all_kernel(
    const float4* __restrict__ x,
    const float4* __restrict__ w0, const float4* __restrict__ w1,
    const float4* __restrict__ w2, const float4* __restrict__ w3,
    uint2* __restrict__ xhi, uint2* __restrict__ xlo,
    uint2* __restrict__ whi, uint2* __restrict__ wlo)
{
    const int region = blockIdx.x >> 10;
    const int bl     = blockIdx.x & 1023;
    const float4* src; uint2 *ph, *pl;
    switch (region) {
        case 0:  src = x;           ph = xhi;            pl = xlo;            break;
        case 1:  src = x + REG4;    ph = xhi + REG4;     pl = xlo + REG4;     break;
        case 2:  src = w0;          ph = whi;            pl = wlo;            break;
        case 3:  src = w1;          ph = whi + REG4;     pl = wlo + REG4;     break;
        case 4:  src = w2;          ph = whi + 2*REG4;   pl = wlo + 2*REG4;   break;
        default: src = w3;          ph = whi + 3*REG4;   pl = wlo + 3*REG4;   break;
    }
    int base = bl * 256 + threadIdx.x;
#pragma unroll
    for (int t = 0; t < 4; t++) {
        int i = base + t * (REG4 / 4);
        float4 v = src[i];
        uint2 hv, lv;
        hv.x = split2(v.x, v.y, lv.x);
        hv.y = split2(v.z, v.w, lv.y);
        ph[i] = hv; pl[i] = lv;
    }
}

// ---------------------------------------------------------------------------
// HMMA bf16-split GEMM NT: C[M,N] = A[M,K] * B[N,K]^T (fp32, 3 products)
// CTA 128x128, BK=64, 256 threads (8 warps, warp tile 64x32), 3-stage pipe.
// Register headroom: acc 64 + frags ~36 << 255-reg budget -> no spills.
// ---------------------------------------------------------------------------
#define GTHREADS 256
#define APITCH   144                      // 64 bf16 = 128B + 16B pad
#define ASZ      (128 * APITCH)           // 18432
#define STAGE_SZ (4 * ASZ)                // Ah,Al,Bh,Bl = 73728
#define GEMM_SMEM (3 * STAGE_SZ)          // 221184

__device__ __forceinline__ void g2s_stage(
    uint32_t sbase, const __nv_bfloat16* pAh, const __nv_bfloat16* pAl,
    const __nv_bfloat16* pBh, const __nv_bfloat16* pBl, int kc, int tid)
{
#pragma unroll
    for (int t = 0; t < 4; t++) {
        int idx = tid + t * GTHREADS;       // 0..1023
        int row = idx >> 3;                 // 0..127
        int c16 = idx & 7;
        uint32_t d = sbase + row * APITCH + c16 * 16;
        size_t g = (size_t)row * D_MOD + kc + c16 * 8;
        CP_ASYNC16(d,           pAh + g);
        CP_ASYNC16(d + ASZ,     pAl + g);
        CP_ASYNC16(d + 2 * ASZ, pBh + g);
        CP_ASYNC16(d + 3 * ASZ, pBl + g);
    }
}

// fills acc[4][4][4] (warp tile 64x32); callers sync before reusing smem
__device__ __forceinline__ void gemm_mainloop(
    uint32_t sb, const __nv_bfloat16* pAh, const __nv_bfloat16* pAl,
    const __nv_bfloat16* pBh, const __nv_bfloat16* pBl,
    int tid, int wm, int wn, int lane, float acc[4][4][4])
{
#pragma unroll
    for (int i = 0; i < 4; i++)
#pragma unroll
        for (int j = 0; j < 4; j++)
#pragma unroll
            for (int e = 0; e < 4; e++) acc[i][j][e] = 0.f;

    const uint32_t a_off = (uint32_t)((lane & 15) * APITCH + (lane >> 4) * 16);
    const uint32_t b_off = (uint32_t)(((lane >> 4) * 8 + (lane & 7)) * APITCH +
                                      ((lane >> 3) & 1) * 16);

    const int nk = D_MOD / 64;   // 32
    g2s_stage(sb + 0 * STAGE_SZ, pAh, pAl, pBh, pBl, 0, tid);
    CP_COMMIT();
    g2s_stage(sb + 1 * STAGE_SZ, pAh, pAl, pBh, pBl, 64, tid);
    CP_COMMIT();

    int stg_idx = 0;
    for (int c = 0; c < nk; c++) {
        const uint32_t stg = sb + stg_idx * STAGE_SZ;
        if (c + 1 < nk) { CP_WAIT1(); } else { CP_WAIT0(); }
        __syncthreads();

        // prefetch chunk c+2 into buffer freed by compute(c-1)
        if (c + 2 < nk) {
            int nidx = stg_idx + 2; if (nidx >= 3) nidx -= 3;
            g2s_stage(sb + nidx * STAGE_SZ, pAh, pAl, pBh, pBl, (c + 2) * 64, tid);
            CP_COMMIT();
        }

#pragma unroll
        for (int s = 0; s < 4; s++) {
            const uint32_t k0b = s * 32;
            uint32_t ah[4][4], al[4][4];
#pragma unroll
            for (int mt = 0; mt < 4; mt++) {
                uint32_t base = stg + (wm * 64 + mt * 16) * APITCH + k0b + a_off;
                ldm_x4(base,       ah[mt][0], ah[mt][1], ah[mt][2], ah[mt][3]);
                ldm_x4(base + ASZ, al[mt][0], al[mt][1], al[mt][2], al[mt][3]);
            }
            uint32_t bh[4][2], bl[4][2];
#pragma unroll
            for (int ntp = 0; ntp < 2; ntp++) {
                uint32_t base = stg + 2 * ASZ + (wn * 32 + ntp * 16) * APITCH + k0b + b_off;
                ldm_x4(base,       bh[2*ntp][0], bh[2*ntp][1], bh[2*ntp+1][0], bh[2*ntp+1][1]);
                ldm_x4(base + ASZ, bl[2*ntp][0], bl[2*ntp][1], bl[2*ntp+1][0], bl[2*ntp+1][1]);
            }
#pragma unroll
            for (int mt = 0; mt < 4; mt++)
#pragma unroll
                for (int nt = 0; nt < 4; nt++) {
                    mma_bf16(acc[mt][nt], ah[mt], bh[nt]);
                    mma_bf16(acc[mt][nt], ah[mt], bl[nt]);
                    mma_bf16(acc[mt][nt], al[mt], bh[nt]);
                }
        }
        if (++stg_idx == 3) stg_idx = 0;
    }
}

// Wo GEMM: fp32 output
__global__ __launch_bounds__(GTHREADS, 1) void gemm_hmma(
    const __nv_bfloat16* __restrict__ Ahi, const __nv_bfloat16* __restrict__ Alo,
    const __nv_bfloat16* __restrict__ Bhi, const __nv_bfloat16* __restrict__ Blo,
    float* __restrict__ C)
{
    extern __shared__ char smem[];
    uint32_t sb = smem_u32(smem);
    const int tid  = threadIdx.x;
    const int wid  = tid >> 5;
    const int lane = tid & 31;
    const int wm   = wid & 1;          // 0..1
    const int wn   = wid >> 1;         // 0..3
    const int bm = blockIdx.y * 128;
    const int bn = blockIdx.x * 128;

    float acc[4][4][4];
    gemm_mainloop(sb, Ahi + (size_t)bm * D_MOD, Alo + (size_t)bm * D_MOD,
                  Bhi + (size_t)bn * D_MOD, Blo + (size_t)bn * D_MOD,
                  tid, wm, wn, lane, acc);

    const int mrow = bm + wm * 64 + (lane >> 2);
    const int ncol = bn + wn * 32 + (lane & 3) * 2;
#pragma unroll
    for (int mt = 0; mt < 4; mt++)
#pragma unroll
        for (int nt = 0; nt < 4; nt++) {
            float* c0 = C + (size_t)(mrow + mt * 16)     * D_MOD + ncol + nt * 8;
            float* c1 = C + (size_t)(mrow + mt * 16 + 8) * D_MOD + ncol + nt * 8;
            *reinterpret_cast<float2*>(c0) = make_float2(acc[mt][nt][0], acc[mt][nt][1]);
            *reinterpret_cast<float2*>(c1) = make_float2(acc[mt][nt][2], acc[mt][nt][3]);
        }
}

// Fused QKV GEMM: z selects weight/output. z<2: RoPE+split epilogue, z=2: split.
#define EPIP 136   // fp32 epilogue smem pitch (128 + 8 pad)
__global__ __launch_bounds__(GTHREADS, 1) void gemm_qkv(
    const __nv_bfloat16* __restrict__ Ahi, const __nv_bfloat16* __restrict__ Alo,
    const __nv_bfloat16* __restrict__ Whi, const __nv_bfloat16* __restrict__ Wlo,
    const float* __restrict__ cosb, const float* __restrict__ sinb,
    uint32_t* __restrict__ qhi, uint32_t* __restrict__ qlo,
    uint32_t* __restrict__ khi, uint32_t* __restrict__ klo,
    uint32_t* __restrict__ vhi, uint32_t* __restrict__ vlo)
{
    extern __shared__ char smem[];
    uint32_t sb = smem_u32(smem);
    const int tid  = threadIdx.x;
    const int wid  = tid >> 5;
    const int lane = tid & 31;
    const int wm   = wid & 1;
    const int wn   = wid >> 1;
    const int bm = blockIdx.y * 128;
    const int bn = blockIdx.x * 128;
    const int z  = blockIdx.z;

    const size_t woff = (size_t)z * D_MOD * D_MOD;
    float acc[4][4][4];
    gemm_mainloop(sb, Ahi + (size_t)bm * D_MOD, Alo + (size_t)bm * D_MOD,
                  Whi + woff + (size_t)bn * D_MOD, Wlo + woff + (size_t)bn * D_MOD,
                  tid, wm, wn, lane, acc);

    if (z == 2) {
        const int mrow = bm + wm * 64 + (lane >> 2);
        const int ncol = bn + wn * 32 + (lane & 3) * 2;
#pragma unroll
        for (int mt = 0; mt < 4; mt++)
#pragma unroll
            for (int nt = 0; nt < 4; nt++) {
                uint32_t lo;
                size_t i0 = ((size_t)(mrow + mt * 16)     * D_MOD + ncol + nt * 8) >> 1;
                size_t i1 = ((size_t)(mrow + mt * 16 + 8) * D_MOD + ncol + nt * 8) >> 1;
                vhi[i0] = split2(acc[mt][nt][0], acc[mt][nt][1], lo); vlo[i0] = lo;
                vhi[i1] = split2(acc[mt][nt][2], acc[mt][nt][3], lo); vlo[i1] = lo;
            }
        return;
    }

    // Q/K: stage acc tile (128x128 fp32) in smem, then RoPE + split.
    __syncthreads();
    float* sf = reinterpret_cast<float*>(smem);
    const int r0 = wm * 64 + (lane >> 2);
    const int c0 = wn * 32 + (lane & 3) * 2;
#pragma unroll
    for (int mt = 0; mt < 4; mt++)
#pragma unroll
        for (int nt = 0; nt < 4; nt++) {
            sf[(r0 + mt * 16)     * EPIP + c0 + nt * 8]     = acc[mt][nt][0];
            sf[(r0 + mt * 16)     * EPIP + c0 + nt * 8 + 1] = acc[mt][nt][1];
            sf[(r0 + mt * 16 + 8) * EPIP + c0 + nt * 8]     = acc[mt][nt][2];
            sf[(r0 + mt * 16 + 8) * EPIP + c0 + nt * 8 + 1] = acc[mt][nt][3];
        }
    __syncthreads();

    uint32_t* OH = z ? khi : qhi;
    uint32_t* OL = z ? klo : qlo;
#pragma unroll
    for (int it = 0; it < 16; it++) {
        int idx = tid + it * GTHREADS;     // 0..4095
        int r = idx >> 5;                  // 0..127
        int d = (idx & 31) * 2;            // 0..62
        float2 v1 = *reinterpret_cast<const float2*>(sf + r * EPIP + d);
        float2 v2 = *reinterpret_cast<const float2*>(sf + r * EPIP + 64 + d);
        int gm = bm + r;
        int srow = gm & (S_LEN - 1);
        float2 c1 = *reinterpret_cast<const float2*>(cosb + srow * HD + d);
        float2 s1 = *reinterpret_cast<const float2*>(sinb + srow * HD + d);
        float2 c2 = *reinterpret_cast<const float2*>(cosb + srow * HD + 64 + d);
        float2 s2 = *reinterpret_cast<const float2*>(sinb + srow * HD + 64 + d);
        float o1x = v1.x * c1.x - v2.x * s1.x;
        float o1y = v1.y * c1.y - v2.y * s1.y;
        float o2x = v2.x * c2.x + v1.x * s2.x;
        float o2y = v2.y * c2.y + v1.y * s2.y;
        size_t base = (size_t)gm * D_MOD + bn;
        uint32_t lo;
        OH[(base + d) >> 1]      = split2(o1x, o1y, lo); OL[(base + d) >> 1]      = lo;
        OH[(base + 64 + d) >> 1] = split2(o2x, o2y, lo); OL[(base + 64 + d) >> 1] = lo;
    }
}

// ---------------------------------------------------------------------------
// Flash attention (causal) with HMMA bf16 3-product split (R13: Q-hi hoisted).
// ---------------------------------------------------------------------------
#define AP    136
#define APB   (AP * 2)
#define QTILE (128 * APB)
#define KVT   (64 * APB)
#define KVSTG (4 * KVT)
#define SKV0  (2 * QTILE)
#define ATTN_SMEM (2 * QTILE + 2 * KVSTG)   // 208896

__device__ __forceinline__ void attn_g2s_kv(
    uint32_t dst, const __nv_bfloat16* kh, const __nv_bfloat16* kl,
    const __nv_bfloat16* vh, const __nv_bfloat16* vl,
    size_t gbase, int tid)
{
    const __nv_bfloat16* ptrs[4] = {kh, kl, vh, vl};
#pragma unroll
    for (int t = 0; t < 4; t++) {
#pragma unroll
        for (int i = 0; i < 4; i++) {
            int idx = tid + i * 256;
            int r = idx >> 4;
            int c = idx & 15;
            CP_ASYNC16(dst + t * KVT + r * APB + c * 16,
                       ptrs[t] + gbase + (size_t)r * D_MOD + c * 8);
        }
    }
}

__global__ __launch_bounds__(256, 1) void attn_mma(
    const __nv_bfloat16* __restrict__ qh_, const __nv_bfloat16* __restrict__ ql_,
    const __nv_bfloat16* __restrict__ kh_, const __nv_bfloat16* __restrict__ kl_,
    const __nv_bfloat16* __restrict__ vh_, const __nv_bfloat16* __restrict__ vl_,
    uint32_t* __restrict__ aohi, uint32_t* __restrict__ aolo)
{
    extern __shared__ char smem[];
    uint32_t sb = smem_u32(smem);
    const int tid  = threadIdx.x;
    const int wid  = tid >> 5;
    const int lane = tid & 31;
    const int bid = blockIdx.x;
    const int qb = 15 - (bid >> 5);
    const int bh = bid & 31;
    const int b  = bh >> 4;
    const int h  = bh & 15;

    const size_t row0 = (size_t)b * S_LEN;
    const int    hoff = h * HD;
    const int    q0   = qb * 128;

    {
        const size_t qg = (row0 + q0) * D_MOD + hoff;
#pragma unroll
        for (int i = 0; i < 8; i++) {
            int idx = tid + i * 256;
            int r = idx >> 4;
            int c = idx & 15;
            uint32_t d = sb + r * APB + c * 16;
            size_t g = qg + (size_t)r * D_MOD + c * 8;
            CP_ASYNC16(d,         qh_ + g);
            CP_ASYNC16(d + QTILE, ql_ + g);
        }
        attn_g2s_kv(sb + SKV0, kh_, kl_, vh_, vl_, row0 * D_MOD + hoff, tid);
        CP_COMMIT();
    }

    float oacc[16][4];
#pragma unroll
    for (int j = 0; j < 16; j++)
#pragma unroll
        for (int e = 0; e < 4; e++) oacc[j][e] = 0.f;
    float m0 = -1e30f, m1 = -1e30f, l0 = 0.f, l1 = 0.f;

    const float sl2 = 0.08838834764831845f * 1.4426950408889634f;
    const int kb_max = qb * 2 + 1;
    const int rg0 = q0 + wid * 16 + (lane >> 2);
    const int rg1 = rg0 + 8;

    const uint32_t a_off = (uint32_t)((lane & 15) * APB + (lane >> 4) * 16);
    const uint32_t b_off = (uint32_t)(((lane >> 4) * 8 + (lane & 7)) * APB +
                                      ((lane >> 3) & 1) * 16);
    const uint32_t v_off = (uint32_t)(((lane & 7) + ((lane >> 3) & 1) * 8) * APB +
                                      (lane >> 4) * 16);

    uint32_t qhR[8][4];
    bool q_loaded = false;

    for (int kb = 0; kb <= kb_max; kb++) {
        if (kb + 1 <= kb_max) {
            attn_g2s_kv(sb + SKV0 + ((kb + 1) & 1) * KVSTG, kh_, kl_, vh_, vl_,
                        (row0 + (kb + 1) * 64) * D_MOD + hoff, tid);
            CP_COMMIT();
            CP_WAIT1();
        } else {
            CP_WAIT0();
        }
        __syncthreads();

        if (!q_loaded) {
            q_loaded = true;
#pragma unroll
            for (int t = 0; t < 8; t++) {
                uint32_t qa = sb + (wid * 16) * APB + t * 32 + a_off;
                ldm_x4(qa, qhR[t][0], qhR[t][1], qhR[t][2], qhR[t][3]);
            }
        }

        const uint32_t stg = sb + SKV0 + (kb & 1) * KVSTG;

        float sacc[8][4];
#pragma unroll
        for (int j = 0; j < 8; j++)
#pragma unroll
            for (int e = 0; e < 4; e++) sacc[j][e] = 0.f;

#pragma unroll
        for (int t = 0; t < 8; t++) {
            uint32_t qa = sb + (wid * 16) * APB + t * 32 + a_off;
            uint32_t qlF[4];
            ldm_x4(qa + QTILE, qlF[0], qlF[1], qlF[2], qlF[3]);
#pragma unroll
            for (int ng = 0; ng < 4; ng++) {
                uint32_t ka = stg + (ng * 16) * APB + t * 32 + b_off;
                uint32_t khF[4], klF[4];
                ldm_x4(ka,       khF[0], khF[1], khF[2], khF[3]);
                ldm_x4(ka + KVT, klF[0], klF[1], klF[2], klF[3]);
                mma_bf16(sacc[2*ng],   qhR[t], khF + 0);
                mma_bf16(sacc[2*ng],   qhR[t], klF + 0);
                mma_bf16(sacc[2*ng],   qlF,    khF + 0);
                mma_bf16(sacc[2*ng+1], qhR[t], khF + 2);
                mma_bf16(sacc[2*ng+1], qhR[t], klF + 2);
                mma_bf16(sacc[2*ng+1], qlF,    khF + 2);
            }
        }

        const bool diag = (kb >= 2 * qb);
        float mx0 = -1e30f, mx1 = -1e30f;
#pragma unroll
        for (int j = 0; j < 8; j++) {
            int colb = kb * 64 + 8 * j + 2 * (lane & 3);
#pragma unroll
            for (int e = 0; e < 4; e++) {
                float v = sacc[j][e] * sl2;
                if (diag) {
                    int col = colb + (e & 1);
                    int row = (e < 2) ? rg0 : rg1;
                    if (col > row) v = -1e30f;
                }
                sacc[j][e] = v;
            }
            mx0 = fmaxf(mx0, fmaxf(sacc[j][0], sacc[j][1]));
            mx1 = fmaxf(mx1, fmaxf(sacc[j][2], sacc[j][3]));
        }
        mx0 = fmaxf(mx0, __shfl_xor_sync(0xffffffffu, mx0, 1));
        mx0 = fmaxf(mx0, __shfl_xor_sync(0xffffffffu, mx0, 2));
        mx1 = fmaxf(mx1, __shfl_xor_sync(0xffffffffu, mx1, 1));
        mx1 = fmaxf(mx1, __shfl_xor_sync(0xffffffffu, mx1, 2));

        float mn0 = fmaxf(m0, mx0), mn1 = fmaxf(m1, mx1);
        float corr0 = ex2f(m0 - mn0), corr1 = ex2f(m1 - mn1);
        m0 = mn0; m1 = mn1;

        float ps0 = 0.f, ps1 = 0.f;
#pragma unroll
        for (int j = 0; j < 8; j++) {
            sacc[j][0] = ex2f(sacc[j][0] - mn0);
            sacc[j][1] = ex2f(sacc[j][1] - mn0);
            sacc[j][2] = ex2f(sacc[j][2] - mn1);
            sacc[j][3] = ex2f(sacc[j][3] - mn1);
            ps0 += sacc[j][0] + sacc[j][1];
            ps1 += sacc[j][2] + sacc[j][3];
        }
        l0 = l0 * corr0 + ps0;
        l1 = l1 * corr1 + ps1;
#pragma unroll
        for (int j = 0; j < 16; j++) {
            oacc[j][0] *= corr0; oacc[j][1] *= corr0;
            oacc[j][2] *= corr1; oacc[j][3] *= corr1;
        }

#pragma unroll
        for (int t = 0; t < 4; t++) {
            uint32_t pah[4], pal[4];
            pah[0] = split2(sacc[2*t][0],   sacc[2*t][1],   pal[0]);
            pah[1] = split2(sacc[2*t][2],   sacc[2*t][3],   pal[1]);
            pah[2] = split2(sacc[2*t+1][0], sacc[2*t+1][1], pal[2]);
            pah[3] = split2(sacc[2*t+1][2], sacc[2*t+1][3], pal[3]);
#pragma unroll
            for (int ng = 0; ng < 8; ng++) {
                uint32_t va = stg + 2 * KVT + (t * 16) * APB + ng * 32 + v_off;
                uint32_t vhF[4], vlF[4];
                ldm_x4t(va,       vhF[0], vhF[1], vhF[2], vhF[3]);
                ldm_x4t(va + KVT, vlF[0], vlF[1], vlF[2], vlF[3]);
                mma_bf16(oacc[2*ng],   pah, vhF + 0);
                mma_bf16(oacc[2*ng],   pah, vlF + 0);
                mma_bf16(oacc[2*ng],   pal, vhF + 0);
                mma_bf16(oacc[2*ng+1], pah, vhF + 2);
                mma_bf16(oacc[2*ng+1], pah, vlF + 2);
                mma_bf16(oacc[2*ng+1], pal, vhF + 2);
            }
        }
        __syncthreads();
    }

    l0 += __shfl_xor_sync(0xffffffffu, l0, 1);
    l0 += __shfl_xor_sync(0xffffffffu, l0, 2);
    l1 += __shfl_xor_sync(0xffffffffu, l1, 1);
    l1 += __shfl_xor_sync(0xffffffffu, l1, 2);
    float inv0 = 1.f / l0, inv1 = 1.f / l1;

    const uint32_t i0 = (uint32_t)(((row0 + rg0) * D_MOD + hoff + 2 * (lane & 3)) >> 1);
    const uint32_t i1 = (uint32_t)(((row0 + rg1) * D_MOD + hoff + 2 * (lane & 3)) >> 1);
#pragma unroll
    for (int j = 0; j < 16; j++) {
        uint32_t lo;
        uint32_t hi = split2(oacc[j][0] * inv0, oacc[j][1] * inv0, lo);
        aohi[i0 + 4 * j] = hi; aolo[i0 + 4 * j] = lo;
        hi = split2(oacc[j][2] * inv1, oacc[j][3] * inv1, lo);
        aohi[i1 + 4 * j] = hi; aolo[i1 + 4 * j] = lo;
    }
}

// ---------------------------------------------------------------------------
extern "C" void kernel_launch(void* const* d_in, const int* in_sizes, int n_in,
                              void* d_out, int out_size)
{
    const float* x    = (const float*)d_in[0];
    const float* cosb = (const float*)d_in[1];
    const float* sinb = (const float*)d_in[2];
    const float* Wq   = (const float*)d_in[3];
    const float* Wk   = (const float*)d_in[4];
    const float* Wv   = (const float*)d_in[5];
    const float* Wo   = (const float*)d_in[6];
    float* out = (float*)d_out;

    __nv_bfloat16 *xhi, *xlo, *whi, *wlo, *aohi, *aolo;
    __nv_bfloat16 *qhi, *qlo, *khi, *klo, *vhi, *vlo;
    cudaGetSymbolAddress((void**)&xhi,  g_xhi);
    cudaGetSymbolAddress((void**)&xlo,  g_xlo);
    cudaGetSymbolAddress((void**)&whi,  g_whi);
    cudaGetSymbolAddress((void**)&wlo,  g_wlo);
    cudaGetSymbolAddress((void**)&aohi, g_aohi);
    cudaGetSymbolAddress((void**)&aolo, g_aolo);
    cudaGetSymbolAddress((void**)&qhi,  g_qhi);
    cudaGetSymbolAddress((void**)&qlo,  g_qlo);
    cudaGetSymbolAddress((void**)&khi,  g_khi);
    cudaGetSymbolAddress((void**)&klo,  g_klo);
    cudaGetSymbolAddress((void**)&vhi,  g_vhi);
    cudaGetSymbolAddress((void**)&vlo,  g_vlo);

    cudaFuncSetAttribute(gemm_hmma,
                         cudaFuncAttributeMaxDynamicSharedMemorySize, GEMM_SMEM);
    cudaFuncSetAttribute(gemm_qkv,
                         cudaFuncAttributeMaxDynamicSharedMemorySize, GEMM_SMEM);
    cudaFuncSetAttribute(attn_mma,
                         cudaFuncAttributeMaxDynamicSharedMemorySize, ATTN_SMEM);

    split_all_kernel<<<6144, 256>>>(
        (const float4*)x, (const float4*)Wq, (const float4*)Wk,
        (const float4*)Wv, (const float4*)Wo,
        (uint2*)xhi, (uint2*)xlo, (uint2*)whi, (uint2*)wlo);

    dim3 qkvgrid(D_MOD / 128, M_TOT / 128, 3);   // (16, 32, 3)
    gemm_qkv<<<qkvgrid, GTHREADS, GEMM_SMEM>>>(xhi, xlo, whi, wlo, cosb, sinb,
        (uint32_t*)qhi, (uint32_t*)qlo, (uint32_t*)khi, (uint32_t*)klo,
        (uint32_t*)vhi, (uint32_t*)vlo);

    attn_mma<<<BATCH * NHEAD * (S_LEN / 128), 256, ATTN_SMEM>>>(
        qhi, qlo, khi, klo, vhi, vlo, (uint32_t*)aohi, (uint32_t*)aolo);

    dim3 ggrid(D_MOD / 128, M_TOT / 128);   // (16, 32)
    gemm_hmma<<<ggrid, GTHREADS, GEMM_SMEM>>>(aohi, aolo,
        whi + 3 * (size_t)D_MOD * D_MOD, wlo + 3 * (size_t)D_MOD * D_MOD, out);
}

// round 15
// speedup vs baseline: 1.0196x; 1.0196x over previous
#include <cuda_runtime.h>
#include <cuda_bf16.h>
#include <math.h>
#include <cstdint>

#define S_LEN   2048
#define D_MOD   2048
#define NHEAD   16
#define HD      128
#define BATCH   2
#define M_TOT   (BATCH * S_LEN)   // 4096

// ---------------------------------------------------------------------------
// helpers
// ---------------------------------------------------------------------------
__device__ __forceinline__ uint32_t smem_u32(const void* p) {
    uint32_t a;
    asm("{ .reg .u64 t; cvta.to.shared.u64 t, %1; cvt.u32.u64 %0, t; }"
        : "=r"(a) : "l"(p));
    return a;
}

#define CP_ASYNC16(dst, src) \
    asm volatile("cp.async.cg.shared.global [%0], [%1], 16;" \
                 :: "r"(dst), "l"(src) : "memory")
#define CP_COMMIT() asm volatile("cp.async.commit_group;" ::: "memory")
#define CP_WAIT1()  asm volatile("cp.async.wait_group 1;" ::: "memory")
#define CP_WAIT0()  asm volatile("cp.async.wait_group 0;" ::: "memory")

__device__ __forceinline__ void ldm_x4(uint32_t addr, uint32_t& r0, uint32_t& r1,
                                       uint32_t& r2, uint32_t& r3) {
    asm volatile("ldmatrix.sync.aligned.m8n8.x4.shared.b16 {%0,%1,%2,%3}, [%4];"
                 : "=r"(r0), "=r"(r1), "=r"(r2), "=r"(r3) : "r"(addr));
}
__device__ __forceinline__ void ldm_x4t(uint32_t addr, uint32_t& r0, uint32_t& r1,
                                        uint32_t& r2, uint32_t& r3) {
    asm volatile("ldmatrix.sync.aligned.m8n8.x4.trans.shared.b16 {%0,%1,%2,%3}, [%4];"
                 : "=r"(r0), "=r"(r1), "=r"(r2), "=r"(r3) : "r"(addr));
}
__device__ __forceinline__ void mma_bf16(float* d, const uint32_t* a, const uint32_t* b) {
    asm volatile(
        "mma.sync.aligned.m16n8k16.row.col.f32.bf16.bf16.f32 "
        "{%0,%1,%2,%3}, {%4,%5,%6,%7}, {%8,%9}, {%0,%1,%2,%3};"
        : "+f"(d[0]), "+f"(d[1]), "+f"(d[2]), "+f"(d[3])
        : "r"(a[0]), "r"(a[1]), "r"(a[2]), "r"(a[3]), "r"(b[0]), "r"(b[1]));
}
__device__ __forceinline__ uint32_t bf16x2_pack(float lo, float hi) {
    uint32_t r;
    asm("cvt.rn.bf16x2.f32 %0, %1, %2;" : "=r"(r) : "f"(hi), "f"(lo));
    return r;
}
__device__ __forceinline__ uint32_t split2(float a, float b, uint32_t& lo) {
    uint32_t h = bf16x2_pack(a, b);
    float ha = __uint_as_float(h << 16);
    float hb = __uint_as_float(h & 0xffff0000u);
    lo = bf16x2_pack(a - ha, b - hb);
    return h;
}
__device__ __forceinline__ float ex2f(float x) {
    float y; asm("ex2.approx.ftz.f32 %0, %1;" : "=f"(y) : "f"(x)); return y;
}

// ---------------------------------------------------------------------------
// Scratch (device globals: allocation-free rule)
// ---------------------------------------------------------------------------
__device__ __nv_bfloat16 g_xhi [M_TOT * D_MOD];
__device__ __nv_bfloat16 g_xlo [M_TOT * D_MOD];
__device__ __nv_bfloat16 g_whi [4][D_MOD * D_MOD];
__device__ __nv_bfloat16 g_wlo [4][D_MOD * D_MOD];
__device__ __nv_bfloat16 g_aohi[M_TOT * D_MOD];
__device__ __nv_bfloat16 g_aolo[M_TOT * D_MOD];
__device__ __nv_bfloat16 g_qhi [M_TOT * D_MOD];
__device__ __nv_bfloat16 g_qlo [M_TOT * D_MOD];
__device__ __nv_bfloat16 g_khi [M_TOT * D_MOD];
__device__ __nv_bfloat16 g_klo [M_TOT * D_MOD];
__device__ __nv_bfloat16 g_vhi [M_TOT * D_MOD];
__device__ __nv_bfloat16 g_vlo [M_TOT * D_MOD];

// ---------------------------------------------------------------------------
// Fused split: x (2 regions) + 4 weights (1 region each) -> hi/lo bf16.
// ---------------------------------------------------------------------------
#define REG4 (1024 * 1024)     // float4 per region
__global__ __launch_bounds__(256) void split_all_kernel(
    const float4* __restrict__ x,
    const float4* __restrict__ w0, const float4* __restrict__ w1,
    const float4* __restrict__ w2, const float4* __restrict__ w3,
    uint2* __restrict__ xhi, uint2* __restrict__ xlo,
    uint2* __restrict__ whi, uint2* __restrict__ wlo)
{
    const int region = blockIdx.x >> 10;
    const int bl     = blockIdx.x & 1023;
    const float4* src; uint2 *ph, *pl;
    switch (region) {
        case 0:  src = x;           ph = xhi;            pl = xlo;            break;
        case 1:  src = x + REG4;    ph = xhi + REG4;     pl = xlo + REG4;     break;
        case 2:  src = w0;          ph = whi;            pl = wlo;            break;
        case 3:  src = w1;          ph = whi + REG4;     pl = wlo + REG4;     break;
        case 4:  src = w2;          ph = whi + 2*REG4;   pl = wlo + 2*REG4;   break;
        default: src = w3;          ph = whi + 3*REG4;   pl = wlo + 3*REG4;   break;
    }
    int base = bl * 256 + threadIdx.x;
#pragma unroll
    for (int t = 0; t < 4; t++) {
        int i = base + t * (REG4 / 4);
        float4 v = src[i];
        uint2 hv, lv;
        hv.x = split2(v.x, v.y, lv.x);
        hv.y = split2(v.z, v.w, lv.y);
        ph[i] = hv; pl[i] = lv;
    }
}

// ---------------------------------------------------------------------------
// HMMA bf16-split GEMM NT: C[M,N] = A[M,K] * B[N,K]^T (fp32, 3 products)
// CTA 128x128, BK=32, 256 threads (8 warps, warp tile 64x32), 2-stage pipe.
// smem 80KB/CTA -> 2 CTAs/SM for cross-CTA latency hiding.
// ---------------------------------------------------------------------------
#define GTHREADS 256
#define TPITCH   80
#define TSZ      (128 * TPITCH)           // 10240
#define STAGE_SZ (4 * TSZ)                // Ah,Al,Bh,Bl = 40960
#define GEMM_SMEM (2 * STAGE_SZ)          // 81920

__device__ __forceinline__ void g2s_stage(
    uint32_t sbase, const __nv_bfloat16* pAh, const __nv_bfloat16* pAl,
    const __nv_bfloat16* pBh, const __nv_bfloat16* pBl, int kc, int tid)
{
#pragma unroll
    for (int t = 0; t < 2; t++) {
        int idx = tid + t * GTHREADS;       // 0..511
        int row = idx >> 2;                 // 0..127
        int c16 = idx & 3;
        uint32_t d = sbase + row * TPITCH + c16 * 16;
        size_t g = (size_t)row * D_MOD + kc + c16 * 8;
        CP_ASYNC16(d,           pAh + g);
        CP_ASYNC16(d + TSZ,     pAl + g);
        CP_ASYNC16(d + 2 * TSZ, pBh + g);
        CP_ASYNC16(d + 3 * TSZ, pBl + g);
    }
}

// fills acc[4][4][4] (warp tile 64x32); callers sync before reusing smem
__device__ __forceinline__ void gemm_mainloop(
    uint32_t sb, const __nv_bfloat16* pAh, const __nv_bfloat16* pAl,
    const __nv_bfloat16* pBh, const __nv_bfloat16* pBl,
    int tid, int wm, int wn, int lane, float acc[4][4][4])
{
#pragma unroll
    for (int i = 0; i < 4; i++)
#pragma unroll
        for (int j = 0; j < 4; j++)
#pragma unroll
            for (int e = 0; e < 4; e++) acc[i][j][e] = 0.f;

    const uint32_t a_off = (uint32_t)((lane & 15) * TPITCH + (lane >> 4) * 16);
    const uint32_t b_off = (uint32_t)(((lane >> 4) * 8 + (lane & 7)) * TPITCH +
                                      ((lane >> 3) & 1) * 16);

    const int nk = D_MOD / 32;   // 64
    g2s_stage(sb, pAh, pAl, pBh, pBl, 0, tid);
    CP_COMMIT();

    for (int c = 0; c < nk; c++) {
        const uint32_t stg = sb + (c & 1) * STAGE_SZ;
        CP_WAIT0();
        __syncthreads();

        if (c + 1 < nk) {
            g2s_stage(sb + ((c + 1) & 1) * STAGE_SZ, pAh, pAl, pBh, pBl,
                      (c + 1) * 32, tid);
            CP_COMMIT();
        }

#pragma unroll
        for (int s = 0; s < 2; s++) {
            const uint32_t k0b = s * 32;
            uint32_t ah[4][4], al[4][4];
#pragma unroll
            for (int mt = 0; mt < 4; mt++) {
                uint32_t base = stg + (wm * 64 + mt * 16) * TPITCH + k0b + a_off;
                ldm_x4(base,       ah[mt][0], ah[mt][1], ah[mt][2], ah[mt][3]);
                ldm_x4(base + TSZ, al[mt][0], al[mt][1], al[mt][2], al[mt][3]);
            }
            uint32_t bh[4][2], bl[4][2];
#pragma unroll
            for (int ntp = 0; ntp < 2; ntp++) {
                uint32_t base = stg + 2 * TSZ + (wn * 32 + ntp * 16) * TPITCH + k0b + b_off;
                ldm_x4(base,       bh[2*ntp][0], bh[2*ntp][1], bh[2*ntp+1][0], bh[2*ntp+1][1]);
                ldm_x4(base + TSZ, bl[2*ntp][0], bl[2*ntp][1], bl[2*ntp+1][0], bl[2*ntp+1][1]);
            }
#pragma unroll
            for (int mt = 0; mt < 4; mt++)
#pragma unroll
                for (int nt = 0; nt < 4; nt++) {
                    mma_bf16(acc[mt][nt], ah[mt], bh[nt]);
                    mma_bf16(acc[mt][nt], ah[mt], bl[nt]);
                    mma_bf16(acc[mt][nt], al[mt], bh[nt]);
                }
        }
    }
}

// Wo GEMM: fp32 output
__global__ __launch_bounds__(GTHREADS, 2) void gemm_hmma(
    const __nv_bfloat16* __restrict__ Ahi, const __nv_bfloat16* __restrict__ Alo,
    const __nv_bfloat16* __restrict__ Bhi, const __nv_bfloat16* __restrict__ Blo,
    float* __restrict__ C)
{
    extern __shared__ char smem[];
    uint32_t sb = smem_u32(smem);
    const int tid  = threadIdx.x;
    const int wid  = tid >> 5;
    const int lane = tid & 31;
    const int wm   = wid & 1;          // 0..1
    const int wn   = wid >> 1;         // 0..3
    const int bm = blockIdx.y * 128;
    const int bn = blockIdx.x * 128;

    float acc[4][4][4];
    gemm_mainloop(sb, Ahi + (size_t)bm * D_MOD, Alo + (size_t)bm * D_MOD,
                  Bhi + (size_t)bn * D_MOD, Blo + (size_t)bn * D_MOD,
                  tid, wm, wn, lane, acc);

    const int mrow = bm + wm * 64 + (lane >> 2);
    const int ncol = bn + wn * 32 + (lane & 3) * 2;
#pragma unroll
    for (int mt = 0; mt < 4; mt++)
#pragma unroll
        for (int nt = 0; nt < 4; nt++) {
            float* c0 = C + (size_t)(mrow + mt * 16)     * D_MOD + ncol + nt * 8;
            float* c1 = C + (size_t)(mrow + mt * 16 + 8) * D_MOD + ncol + nt * 8;
            *reinterpret_cast<float2*>(c0) = make_float2(acc[mt][nt][0], acc[mt][nt][1]);
            *reinterpret_cast<float2*>(c1) = make_float2(acc[mt][nt][2], acc[mt][nt][3]);
        }
}

// Fused QKV GEMM: z selects weight/output. z<2: RoPE+split epilogue, z=2: split.
#define EPIP 136   // fp32 epilogue smem pitch (128 + 8 pad) -> 69632 B < 81920
__global__ __launch_bounds__(GTHREADS, 2) void gemm_qkv(
    const __nv_bfloat16* __restrict__ Ahi, const __nv_bfloat16* __restrict__ Alo,
    const __nv_bfloat16* __restrict__ Whi, const __nv_bfloat16* __restrict__ Wlo,
    const float* __restrict__ cosb, const float* __restrict__ sinb,
    uint32_t* __restrict__ qhi, uint32_t* __restrict__ qlo,
    uint32_t* __restrict__ khi, uint32_t* __restrict__ klo,
    uint32_t* __restrict__ vhi, uint32_t* __restrict__ vlo)
{
    extern __shared__ char smem[];
    uint32_t sb = smem_u32(smem);
    const int tid  = threadIdx.x;
    const int wid  = tid >> 5;
    const int lane = tid & 31;
    const int wm   = wid & 1;
    const int wn   = wid >> 1;
    const int bm = blockIdx.y * 128;
    const int bn = blockIdx.x * 128;
    const int z  = blockIdx.z;

    const size_t woff = (size_t)z * D_MOD * D_MOD;
    float acc[4][4][4];
    gemm_mainloop(sb, Ahi + (size_t)bm * D_MOD, Alo + (size_t)bm * D_MOD,
                  Whi + woff + (size_t)bn * D_MOD, Wlo + woff + (size_t)bn * D_MOD,
                  tid, wm, wn, lane, acc);

    if (z == 2) {
        const int mrow = bm + wm * 64 + (lane >> 2);
        const int ncol = bn + wn * 32 + (lane & 3) * 2;
#pragma unroll
        for (int mt = 0; mt < 4; mt++)
#pragma unroll
            for (int nt = 0; nt < 4; nt++) {
                uint32_t lo;
                size_t i0 = ((size_t)(mrow + mt * 16)     * D_MOD + ncol + nt * 8) >> 1;
                size_t i1 = ((size_t)(mrow + mt * 16 + 8) * D_MOD + ncol + nt * 8) >> 1;
                vhi[i0] = split2(acc[mt][nt][0], acc[mt][nt][1], lo); vlo[i0] = lo;
                vhi[i1] = split2(acc[mt][nt][2], acc[mt][nt][3], lo); vlo[i1] = lo;
            }
        return;
    }

    // Q/K: stage acc tile (128x128 fp32) in smem, then RoPE + split.
    __syncthreads();
    float* sf = reinterpret_cast<float*>(smem);
    const int r0 = wm * 64 + (lane >> 2);
    const int c0 = wn * 32 + (lane & 3) * 2;
#pragma unroll
    for (int mt = 0; mt < 4; mt++)
#pragma unroll
        for (int nt = 0; nt < 4; nt++) {
            sf[(r0 + mt * 16)     * EPIP + c0 + nt * 8]     = acc[mt][nt][0];
            sf[(r0 + mt * 16)     * EPIP + c0 + nt * 8 + 1] = acc[mt][nt][1];
            sf[(r0 + mt * 16 + 8) * EPIP + c0 + nt * 8]     = acc[mt][nt][2];
            sf[(r0 + mt * 16 + 8) * EPIP + c0 + nt * 8 + 1] = acc[mt][nt][3];
        }
    __syncthreads();

    uint32_t* OH = z ? khi : qhi;
    uint32_t* OL = z ? klo : qlo;
#pragma unroll
    for (int it = 0; it < 16; it++) {
        int idx = tid + it * GTHREADS;     // 0..4095
        int r = idx >> 5;                  // 0..127
        int d = (idx & 31) * 2;            // 0..62
        float2 v1 = *reinterpret_cast<const float2*>(sf + r * EPIP + d);
        float2 v2 = *reinterpret_cast<const float2*>(sf + r * EPIP + 64 + d);
        int gm = bm + r;
        int srow = gm & (S_LEN - 1);
        float2 c1 = *reinterpret_cast<const float2*>(cosb + srow * HD + d);
        float2 s1 = *reinterpret_cast<const float2*>(sinb + srow * HD + d);
        float2 c2 = *reinterpret_cast<const float2*>(cosb + srow * HD + 64 + d);
        float2 s2 = *reinterpret_cast<const float2*>(sinb + srow * HD + 64 + d);
        float o1x = v1.x * c1.x - v2.x * s1.x;
        float o1y = v1.y * c1.y - v2.y * s1.y;
        float o2x = v2.x * c2.x + v1.x * s2.x;
        float o2y = v2.y * c2.y + v1.y * s2.y;
        size_t base = (size_t)gm * D_MOD + bn;
        uint32_t lo;
        OH[(base + d) >> 1]      = split2(o1x, o1y, lo); OL[(base + d) >> 1]      = lo;
        OH[(base + 64 + d) >> 1] = split2(o2x, o2y, lo); OL[(base + 64 + d) >> 1] = lo;
    }
}

// ---------------------------------------------------------------------------
// Flash attention (causal) with HMMA bf16 3-product split (R13: Q-hi hoisted).
// ---------------------------------------------------------------------------
#define AP    136
#define APB   (AP * 2)
#define QTILE (128 * APB)
#define KVT   (64 * APB)
#define KVSTG (4 * KVT)
#define SKV0  (2 * QTILE)
#define ATTN_SMEM (2 * QTILE + 2 * KVSTG)   // 208896

__device__ __forceinline__ void attn_g2s_kv(
    uint32_t dst, const __nv_bfloat16* kh, const __nv_bfloat16* kl,
    const __nv_bfloat16* vh, const __nv_bfloat16* vl,
    size_t gbase, int tid)
{
    const __nv_bfloat16* ptrs[4] = {kh, kl, vh, vl};
#pragma unroll
    for (int t = 0; t < 4; t++) {
#pragma unroll
        for (int i = 0; i < 4; i++) {
            int idx = tid + i * 256;
            int r = idx >> 4;
            int c = idx & 15;
            CP_ASYNC16(dst + t * KVT + r * APB + c * 16,
                       ptrs[t] + gbase + (size_t)r * D_MOD + c * 8);
        }
    }
}

__global__ __launch_bounds__(256, 1) void attn_mma(
    const __nv_bfloat16* __restrict__ qh_, const __nv_bfloat16* __restrict__ ql_,
    const __nv_bfloat16* __restrict__ kh_, const __nv_bfloat16* __restrict__ kl_,
    const __nv_bfloat16* __restrict__ vh_, const __nv_bfloat16* __restrict__ vl_,
    uint32_t* __restrict__ aohi, uint32_t* __restrict__ aolo)
{
    extern __shared__ char smem[];
    uint32_t sb = smem_u32(smem);
    const int tid  = threadIdx.x;
    const int wid  = tid >> 5;
    const int lane = tid & 31;
    const int bid = blockIdx.x;
    const int qb = 15 - (bid >> 5);
    const int bh = bid & 31;
    const int b  = bh >> 4;
    const int h  = bh & 15;

    const size_t row0 = (size_t)b * S_LEN;
    const int    hoff = h * HD;
    const int    q0   = qb * 128;

    {
        const size_t qg = (row0 + q0) * D_MOD + hoff;
#pragma unroll
        for (int i = 0; i < 8; i++) {
            int idx = tid + i * 256;
            int r = idx >> 4;
            int c = idx & 15;
            uint32_t d = sb + r * APB + c * 16;
            size_t g = qg + (size_t)r * D_MOD + c * 8;
            CP_ASYNC16(d,         qh_ + g);
            CP_ASYNC16(d + QTILE, ql_ + g);
        }
        attn_g2s_kv(sb + SKV0, kh_, kl_, vh_, vl_, row0 * D_MOD + hoff, tid);
        CP_COMMIT();
    }

    float oacc[16][4];
#pragma unroll
    for (int j = 0; j < 16; j++)
#pragma unroll
        for (int e = 0; e < 4; e++) oacc[j][e] = 0.f;
    float m0 = -1e30f, m1 = -1e30f, l0 = 0.f, l1 = 0.f;

    const float sl2 = 0.08838834764831845f * 1.4426950408889634f;
    const int kb_max = qb * 2 + 1;
    const int rg0 = q0 + wid * 16 + (lane >> 2);
    const int rg1 = rg0 + 8;

    const uint32_t a_off = (uint32_t)((lane & 15) * APB + (lane >> 4) * 16);
    const uint32_t b_off = (uint32_t)(((lane >> 4) * 8 + (lane & 7)) * APB +
                                      ((lane >> 3) & 1) * 16);
    const uint32_t v_off = (uint32_t)(((lane & 7) + ((lane >> 3) & 1) * 8) * APB +
                                      (lane >> 4) * 16);

    uint32_t qhR[8][4];
    bool q_loaded = false;

    for (int kb = 0; kb <= kb_max; kb++) {
        if (kb + 1 <= kb_max) {
            attn_g2s_kv(sb + SKV0 + ((kb + 1) & 1) * KVSTG, kh_, kl_, vh_, vl_,
                        (row0 + (kb + 1) * 64) * D_MOD + hoff, tid);
            CP_COMMIT();
            CP_WAIT1();
        } else {
            CP_WAIT0();
        }
        __syncthreads();

        if (!q_loaded) {
            q_loaded = true;
#pragma unroll
            for (int t = 0; t < 8; t++) {
                uint32_t qa = sb + (wid * 16) * APB + t * 32 + a_off;
                ldm_x4(qa, qhR[t][0], qhR[t][1], qhR[t][2], qhR[t][3]);
            }
        }

        const uint32_t stg = sb + SKV0 + (kb & 1) * KVSTG;

        float sacc[8][4];
#pragma unroll
        for (int j = 0; j < 8; j++)
#pragma unroll
            for (int e = 0; e < 4; e++) sacc[j][e] = 0.f;

#pragma unroll
        for (int t = 0; t < 8; t++) {
            uint32_t qa = sb + (wid * 16) * APB + t * 32 + a_off;
            uint32_t qlF[4];
            ldm_x4(qa + QTILE, qlF[0], qlF[1], qlF[2], qlF[3]);
#pragma unroll
            for (int ng = 0; ng < 4; ng++) {
                uint32_t ka = stg + (ng * 16) * APB + t * 32 + b_off;
                uint32_t khF[4], klF[4];
                ldm_x4(ka,       khF[0], khF[1], khF[2], khF[3]);
                ldm_x4(ka + KVT, klF[0], klF[1], klF[2], klF[3]);
                mma_bf16(sacc[2*ng],   qhR[t], khF + 0);
                mma_bf16(sacc[2*ng],   qhR[t], klF + 0);
                mma_bf16(sacc[2*ng],   qlF,    khF + 0);
                mma_bf16(sacc[2*ng+1], qhR[t], khF + 2);
                mma_bf16(sacc[2*ng+1], qhR[t], klF + 2);
                mma_bf16(sacc[2*ng+1], qlF,    khF + 2);
            }
        }

        const bool diag = (kb >= 2 * qb);
        float mx0 = -1e30f, mx1 = -1e30f;
#pragma unroll
        for (int j = 0; j < 8; j++) {
            int colb = kb * 64 + 8 * j + 2 * (lane & 3);
#pragma unroll
            for (int e = 0; e < 4; e++) {
                float v = sacc[j][e] * sl2;
                if (diag) {
                    int col = colb + (e & 1);
                    int row = (e < 2) ? rg0 : rg1;
                    if (col > row) v = -1e30f;
                }
                sacc[j][e] = v;
            }
            mx0 = fmaxf(mx0, fmaxf(sacc[j][0], sacc[j][1]));
            mx1 = fmaxf(mx1, fmaxf(sacc[j][2], sacc[j][3]));
        }
        mx0 = fmaxf(mx0, __shfl_xor_sync(0xffffffffu, mx0, 1));
        mx0 = fmaxf(mx0, __shfl_xor_sync(0xffffffffu, mx0, 2));
        mx1 = fmaxf(mx1, __shfl_xor_sync(0xffffffffu, mx1, 1));
        mx1 = fmaxf(mx1, __shfl_xor_sync(0xffffffffu, mx1, 2));

        float mn0 = fmaxf(m0, mx0), mn1 = fmaxf(m1, mx1);
        float corr0 = ex2f(m0 - mn0), corr1 = ex2f(m1 - mn1);
        m0 = mn0; m1 = mn1;

        float ps0 = 0.f, ps1 = 0.f;
#pragma unroll
        for (int j = 0; j < 8; j++) {
            sacc[j][0] = ex2f(sacc[j][0] - mn0);
            sacc[j][1] = ex2f(sacc[j][1] - mn0);
            sacc[j][2] = ex2f(sacc[j][2] - mn1);
            sacc[j][3] = ex2f(sacc[j][3] - mn1);
            ps0 += sacc[j][0] + sacc[j][1];
            ps1 += sacc[j][2] + sacc[j][3];
        }
        l0 = l0 * corr0 + ps0;
        l1 = l1 * corr1 + ps1;
#pragma unroll
        for (int j = 0; j < 16; j++) {
            oacc[j][0] *= corr0; oacc[j][1] *= corr0;
            oacc[j][2] *= corr1; oacc[j][3] *= corr1;
        }

#pragma unroll
        for (int t = 0; t < 4; t++) {
            uint32_t pah[4], pal[4];
            pah[0] = split2(sacc[2*t][0],   sacc[2*t][1],   pal[0]);
            pah[1] = split2(sacc[2*t][2],   sacc[2*t][3],   pal[1]);
            pah[2] = split2(sacc[2*t+1][0], sacc[2*t+1][1], pal[2]);
            pah[3] = split2(sacc[2*t+1][2], sacc[2*t+1][3], pal[3]);
#pragma unroll
            for (int ng = 0; ng < 8; ng++) {
                uint32_t va = stg + 2 * KVT + (t * 16) * APB + ng * 32 + v_off;
                uint32_t vhF[4], vlF[4];
                ldm_x4t(va,       vhF[0], vhF[1], vhF[2], vhF[3]);
                ldm_x4t(va + KVT, vlF[0], vlF[1], vlF[2], vlF[3]);
                mma_bf16(oacc[2*ng],   pah, vhF + 0);
                mma_bf16(oacc[2*ng],   pah, vlF + 0);
                mma_bf16(oacc[2*ng],   pal, vhF + 0);
                mma_bf16(oacc[2*ng+1], pah, vhF + 2);
                mma_bf16(oacc[2*ng+1], pah, vlF + 2);
                mma_bf16(oacc[2*ng+1], pal, vhF + 2);
            }
        }
        __syncthreads();
    }

    l0 += __shfl_xor_sync(0xffffffffu, l0, 1);
    l0 += __shfl_xor_sync(0xffffffffu, l0, 2);
    l1 += __shfl_xor_sync(0xffffffffu, l1, 1);
    l1 += __shfl_xor_sync(0xffffffffu, l1, 2);
    float inv0 = 1.f / l0, inv1 = 1.f / l1;

    const uint32_t i0 = (uint32_t)(((row0 + rg0) * D_MOD + hoff + 2 * (lane & 3)) >> 1);
    const uint32_t i1 = (uint32_t)(((row0 + rg1) * D_MOD + hoff + 2 * (lane & 3)) >> 1);
#pragma unroll
    for (int j = 0; j < 16; j++) {
        uint32_t lo;
        uint32_t hi = split2(oacc[j][0] * inv0, oacc[j][1] * inv0, lo);
        aohi[i0 + 4 * j] = hi; aolo[i0 + 4 * j] = lo;
        hi = split2(oacc[j][2] * inv1, oacc[j][3] * inv1, lo);
        aohi[i1 + 4 * j] = hi; aolo[i1 + 4 * j] = lo;
    }
}

// ---------------------------------------------------------------------------
extern "C" void kernel_launch(void* const* d_in, const int* in_sizes, int n_in,
                              void* d_out, int out_size)
{
    const float* x    = (const float*)d_in[0];
    const float* cosb = (const float*)d_in[1];
    const float* sinb = (const float*)d_in[2];
    const float* Wq   = (const float*)d_in[3];
    const float* Wk   = (const float*)d_in[4];
    const float* Wv   = (const float*)d_in[5];
    const float* Wo   = (const float*)d_in[6];
    float* out = (float*)d_out;

    __nv_bfloat16 *xhi, *xlo, *whi, *wlo, *aohi, *aolo;
    __nv_bfloat16 *qhi, *qlo, *khi, *klo, *vhi, *vlo;
    cudaGetSymbolAddress((void**)&xhi,  g_xhi);
    cudaGetSymbolAddress((void**)&xlo,  g_xlo);
    cudaGetSymbolAddress((void**)&whi,  g_whi);
    cudaGetSymbolAddress((void**)&wlo,  g_wlo);
    cudaGetSymbolAddress((void**)&aohi, g_aohi);
    cudaGetSymbolAddress((void**)&aolo, g_aolo);
    cudaGetSymbolAddress((void**)&qhi,  g_qhi);
    cudaGetSymbolAddress((void**)&qlo,  g_qlo);
    cudaGetSymbolAddress((void**)&khi,  g_khi);
    cudaGetSymbolAddress((void**)&klo,  g_klo);
    cudaGetSymbolAddress((void**)&vhi,  g_vhi);
    cudaGetSymbolAddress((void**)&vlo,  g_vlo);

    cudaFuncSetAttribute(gemm_hmma,
                         cudaFuncAttributeMaxDynamicSharedMemorySize, GEMM_SMEM);
    cudaFuncSetAttribute(gemm_qkv,
                         cudaFuncAttributeMaxDynamicSharedMemorySize, GEMM_SMEM);
    cudaFuncSetAttribute(attn_mma,
                         cudaFuncAttributeMaxDynamicSharedMemorySize, ATTN_SMEM);

    split_all_kernel<<<6144, 256>>>(
        (const float4*)x, (const float4*)Wq, (const float4*)Wk,
        (const float4*)Wv, (const float4*)Wo,
        (uint2*)xhi, (uint2*)xlo, (uint2*)whi, (uint2*)wlo);

    dim3 qkvgrid(D_MOD / 128, M_TOT / 128, 3);   // (16, 32, 3)
    gemm_qkv<<<qkvgrid, GTHREADS, GEMM_SMEM>>>(xhi, xlo, whi, wlo, cosb, sinb,
        (uint32_t*)qhi, (uint32_t*)qlo, (uint32_t*)khi, (uint32_t*)klo,
        (uint32_t*)vhi, (uint32_t*)vlo);

    attn_mma<<<BATCH * NHEAD * (S_LEN / 128), 256, ATTN_SMEM>>>(
        qhi, qlo, khi, klo, vhi, vlo, (uint32_t*)aohi, (uint32_t*)aolo);

    dim3 ggrid(D_MOD / 128, M_TOT / 128);   // (16, 32)
    gemm_hmma<<<ggrid, GTHREADS, GEMM_SMEM>>>(aohi, aolo,
        whi + 3 * (size_t)D_MOD * D_MOD, wlo + 3 * (size_t)D_MOD * D_MOD, out);
}

// round 16
// speedup vs baseline: 1.0239x; 1.0042x over previous
#include <cuda_runtime.h>
#include <cuda_bf16.h>
#include <math.h>
#include <cstdint>

#define S_LEN   2048
#define D_MOD   2048
#define NHEAD   16
#define HD      128
#define BATCH   2
#define M_TOT   (BATCH * S_LEN)   // 4096

// ---------------------------------------------------------------------------
// helpers
// ---------------------------------------------------------------------------
__device__ __forceinline__ uint32_t smem_u32(const void* p) {
    uint32_t a;
    asm("{ .reg .u64 t; cvta.to.shared.u64 t, %1; cvt.u32.u64 %0, t; }"
        : "=r"(a) : "l"(p));
    return a;
}

#define CP_ASYNC16(dst, src) \
    asm volatile("cp.async.cg.shared.global [%0], [%1], 16;" \
                 :: "r"(dst), "l"(src) : "memory")
#define CP_COMMIT() asm volatile("cp.async.commit_group;" ::: "memory")
#define CP_WAIT1()  asm volatile("cp.async.wait_group 1;" ::: "memory")
#define CP_WAIT0()  asm volatile("cp.async.wait_group 0;" ::: "memory")

__device__ __forceinline__ void ldm_x4(uint32_t addr, uint32_t& r0, uint32_t& r1,
                                       uint32_t& r2, uint32_t& r3) {
    asm volatile("ldmatrix.sync.aligned.m8n8.x4.shared.b16 {%0,%1,%2,%3}, [%4];"
                 : "=r"(r0), "=r"(r1), "=r"(r2), "=r"(r3) : "r"(addr));
}
__device__ __forceinline__ void ldm_x4t(uint32_t addr, uint32_t& r0, uint32_t& r1,
                                        uint32_t& r2, uint32_t& r3) {
    asm volatile("ldmatrix.sync.aligned.m8n8.x4.trans.shared.b16 {%0,%1,%2,%3}, [%4];"
                 : "=r"(r0), "=r"(r1), "=r"(r2), "=r"(r3) : "r"(addr));
}
__device__ __forceinline__ void mma_bf16(float* d, const uint32_t* a, const uint32_t* b) {
    asm volatile(
        "mma.sync.aligned.m16n8k16.row.col.f32.bf16.bf16.f32 "
        "{%0,%1,%2,%3}, {%4,%5,%6,%7}, {%8,%9}, {%0,%1,%2,%3};"
        : "+f"(d[0]), "+f"(d[1]), "+f"(d[2]), "+f"(d[3])
        : "r"(a[0]), "r"(a[1]), "r"(a[2]), "r"(a[3]), "r"(b[0]), "r"(b[1]));
}
__device__ __forceinline__ uint32_t bf16x2_pack(float lo, float hi) {
    uint32_t r;
    asm("cvt.rn.bf16x2.f32 %0, %1, %2;" : "=r"(r) : "f"(hi), "f"(lo));
    return r;
}
__device__ __forceinline__ uint32_t split2(float a, float b, uint32_t& lo) {
    uint32_t h = bf16x2_pack(a, b);
    float ha = __uint_as_float(h << 16);
    float hb = __uint_as_float(h & 0xffff0000u);
    lo = bf16x2_pack(a - ha, b - hb);
    return h;
}
__device__ __forceinline__ float ex2f(float x) {
    float y; asm("ex2.approx.ftz.f32 %0, %1;" : "=f"(y) : "f"(x)); return y;
}

// ---------------------------------------------------------------------------
// Scratch (device globals: allocation-free rule)
// ---------------------------------------------------------------------------
__device__ __nv_bfloat16 g_xhi [M_TOT * D_MOD];
__device__ __nv_bfloat16 g_xlo [M_TOT * D_MOD];
__device__ __nv_bfloat16 g_whi [4][D_MOD * D_MOD];
__device__ __nv_bfloat16 g_wlo [4][D_MOD * D_MOD];
__device__ __nv_bfloat16 g_aohi[M_TOT * D_MOD];
__device__ __nv_bfloat16 g_aolo[M_TOT * D_MOD];
__device__ __nv_bfloat16 g_qhi [M_TOT * D_MOD];
__device__ __nv_bfloat16 g_qlo [M_TOT * D_MOD];
__device__ __nv_bfloat16 g_khi [M_TOT * D_MOD];
__device__ __nv_bfloat16 g_klo [M_TOT * D_MOD];
__device__ __nv_bfloat16 g_vhi [M_TOT * D_MOD];
__device__ __nv_bfloat16 g_vlo [M_TOT * D_MOD];

// ---------------------------------------------------------------------------
// Fused split: x (2 regions) + 4 weights (1 region each) -> hi/lo bf16.
// Front-batched loads (MLP=4) to cut latency-bound stalls.
// ---------------------------------------------------------------------------
#define REG4 (1024 * 1024)     // float4 per region
__global__ __launch_bounds__(256) void split_all_kernel(
    const float4* __restrict__ x,
    const float4* __restrict__ w0, const float4* __restrict__ w1,
    const float4* __restrict__ w2, const float4* __restrict__ w3,
    uint2* __restrict__ xhi, uint2* __restrict__ xlo,
    uint2* __restrict__ whi, uint2* __restrict__ wlo)
{
    const int region = blockIdx.x >> 10;
    const int bl     = blockIdx.x & 1023;
    const float4* src; uint2 *ph, *pl;
    switch (region) {
        case 0:  src = x;           ph = xhi;            pl = xlo;            break;
        case 1:  src = x + REG4;    ph = xhi + REG4;     pl = xlo + REG4;     break;
        case 2:  src = w0;          ph = whi;            pl = wlo;            break;
        case 3:  src = w1;          ph = whi + REG4;     pl = wlo + REG4;     break;
        case 4:  src = w2;          ph = whi + 2*REG4;   pl = wlo + 2*REG4;   break;
        default: src = w3;          ph = whi + 3*REG4;   pl = wlo + 3*REG4;   break;
    }
    int base = bl * 256 + threadIdx.x;
    float4 v[4];
#pragma unroll
    for (int t = 0; t < 4; t++)
        v[t] = src[base + t * (REG4 / 4)];
#pragma unroll
    for (int t = 0; t < 4; t++) {
        int i = base + t * (REG4 / 4);
        uint2 hv, lv;
        hv.x = split2(v[t].x, v[t].y, lv.x);
        hv.y = split2(v[t].z, v[t].w, lv.y);
        ph[i] = hv; pl[i] = lv;
    }
}

// ---------------------------------------------------------------------------
// HMMA bf16-split GEMM NT core: C[M,N] = A[M,K] * B[N,K]^T (fp32, 3 products)
// CTA 128x256, BK=64, 512 threads (16 warps, warp tile 64x32), 2-stage pipe.
// ---------------------------------------------------------------------------
#define GTHREADS 512
#define APITCH   144                      // 64 bf16 = 128B + 16B pad
#define ASZ      (128 * APITCH)           // 18432
#define BSZ      (256 * APITCH)           // 36864
#define STAGE_SZ (2 * ASZ + 2 * BSZ)      // 110592
#define GEMM_SMEM (2 * STAGE_SZ)          // 221184

__device__ __forceinline__ void g2s_stage(
    uint32_t sbase, const __nv_bfloat16* pAh, const __nv_bfloat16* pAl,
    const __nv_bfloat16* pBh, const __nv_bfloat16* pBl, int kc, int tid)
{
#pragma unroll
    for (int t = 0; t < 2; t++) {
        int idx = tid + t * GTHREADS;       // 0..1023
        int row = idx >> 3;                 // 0..127
        int c16 = idx & 7;
        uint32_t d = sbase + row * APITCH + c16 * 16;
        size_t g = (size_t)row * D_MOD + kc + c16 * 8;
        CP_ASYNC16(d,       pAh + g);
        CP_ASYNC16(d + ASZ, pAl + g);
    }
#pragma unroll
    for (int t = 0; t < 4; t++) {
        int idx = tid + t * GTHREADS;       // 0..2047
        int row = idx >> 3;                 // 0..255
        int c16 = idx & 7;
        uint32_t d = sbase + 2 * ASZ + row * APITCH + c16 * 16;
        size_t g = (size_t)row * D_MOD + kc + c16 * 8;
        CP_ASYNC16(d,       pBh + g);
        CP_ASYNC16(d + BSZ, pBl + g);
    }
}

// fills acc[4][4][4] (warp tile 64x32); callers sync before reusing smem
__device__ __forceinline__ void gemm_mainloop(
    uint32_t sb, const __nv_bfloat16* pAh, const __nv_bfloat16* pAl,
    const __nv_bfloat16* pBh, const __nv_bfloat16* pBl,
    int tid, int wm, int wn, int lane, float acc[4][4][4])
{
#pragma unroll
    for (int i = 0; i < 4; i++)
#pragma unroll
        for (int j = 0; j < 4; j++)
#pragma unroll
            for (int e = 0; e < 4; e++) acc[i][j][e] = 0.f;

    const uint32_t a_off = (uint32_t)((lane & 15) * APITCH + (lane >> 4) * 16);
    const uint32_t b_off = (uint32_t)(((lane >> 4) * 8 + (lane & 7)) * APITCH +
                                      ((lane >> 3) & 1) * 16);

    const int nk = D_MOD / 64;   // 32
    g2s_stage(sb, pAh, pAl, pBh, pBl, 0, tid);
    CP_COMMIT();

    for (int c = 0; c < nk; c++) {
        const uint32_t stg = sb + (c & 1) * STAGE_SZ;
        CP_WAIT0();
        __syncthreads();

        if (c + 1 < nk) {
            g2s_stage(sb + ((c + 1) & 1) * STAGE_SZ, pAh, pAl, pBh, pBl,
                      (c + 1) * 64, tid);
            CP_COMMIT();
        }

#pragma unroll
        for (int s = 0; s < 4; s++) {
            const uint32_t k0b = s * 32;
            uint32_t ah[4][4], al[4][4];
#pragma unroll
            for (int mt = 0; mt < 4; mt++) {
                uint32_t base = stg + (wm * 64 + mt * 16) * APITCH + k0b + a_off;
                ldm_x4(base,       ah[mt][0], ah[mt][1], ah[mt][2], ah[mt][3]);
                ldm_x4(base + ASZ, al[mt][0], al[mt][1], al[mt][2], al[mt][3]);
            }
            uint32_t bh[4][2], bl[4][2];
#pragma unroll
            for (int ntp = 0; ntp < 2; ntp++) {
                uint32_t base = stg + 2 * ASZ + (wn * 32 + ntp * 16) * APITCH + k0b + b_off;
                ldm_x4(base,       bh[2*ntp][0], bh[2*ntp][1], bh[2*ntp+1][0], bh[2*ntp+1][1]);
                ldm_x4(base + BSZ, bl[2*ntp][0], bl[2*ntp][1], bl[2*ntp+1][0], bl[2*ntp+1][1]);
            }
#pragma unroll
            for (int mt = 0; mt < 4; mt++)
#pragma unroll
                for (int nt = 0; nt < 4; nt++) {
                    mma_bf16(acc[mt][nt], ah[mt], bh[nt]);
                    mma_bf16(acc[mt][nt], ah[mt], bl[nt]);
                    mma_bf16(acc[mt][nt], al[mt], bh[nt]);
                }
        }
    }
}

// Wo GEMM: fp32 output
__global__ __launch_bounds__(GTHREADS, 1) void gemm_hmma(
    const __nv_bfloat16* __restrict__ Ahi, const __nv_bfloat16* __restrict__ Alo,
    const __nv_bfloat16* __restrict__ Bhi, const __nv_bfloat16* __restrict__ Blo,
    float* __restrict__ C)
{
    extern __shared__ char smem[];
    uint32_t sb = smem_u32(smem);
    const int tid  = threadIdx.x;
    const int wid  = tid >> 5;
    const int lane = tid & 31;
    const int wm   = wid & 1;          // 0..1
    const int wn   = wid >> 1;         // 0..7
    const int bm = blockIdx.y * 128;
    const int bn = blockIdx.x * 256;

    float acc[4][4][4];
    gemm_mainloop(sb, Ahi + (size_t)bm * D_MOD, Alo + (size_t)bm * D_MOD,
                  Bhi + (size_t)bn * D_MOD, Blo + (size_t)bn * D_MOD,
                  tid, wm, wn, lane, acc);

    const int mrow = bm + wm * 64 + (lane >> 2);
    const int ncol = bn + wn * 32 + (lane & 3) * 2;
#pragma unroll
    for (int mt = 0; mt < 4; mt++)
#pragma unroll
        for (int nt = 0; nt < 4; nt++) {
            float* c0 = C + (size_t)(mrow + mt * 16)     * D_MOD + ncol + nt * 8;
            float* c1 = C + (size_t)(mrow + mt * 16 + 8) * D_MOD + ncol + nt * 8;
            *reinterpret_cast<float2*>(c0) = make_float2(acc[mt][nt][0], acc[mt][nt][1]);
            *reinterpret_cast<float2*>(c1) = make_float2(acc[mt][nt][2], acc[mt][nt][3]);
        }
}

// Fused QKV GEMM: z selects weight/output. z<2: RoPE+split epilogue, z=2: split.
#define EPIP 264   // fp32 epilogue smem pitch (256 + 8 pad)
__global__ __launch_bounds__(GTHREADS, 1) void gemm_qkv(
    const __nv_bfloat16* __restrict__ Ahi, const __nv_bfloat16* __restrict__ Alo,
    const __nv_bfloat16* __restrict__ Whi, const __nv_bfloat16* __restrict__ Wlo,
    const float* __restrict__ cosb, const float* __restrict__ sinb,
    uint32_t* __restrict__ qhi, uint32_t* __restrict__ qlo,
    uint32_t* __restrict__ khi, uint32_t* __restrict__ klo,
    uint32_t* __restrict__ vhi, uint32_t* __restrict__ vlo)
{
    extern __shared__ char smem[];
    uint32_t sb = smem_u32(smem);
    const int tid  = threadIdx.x;
    const int wid  = tid >> 5;
    const int lane = tid & 31;
    const int wm   = wid & 1;
    const int wn   = wid >> 1;
    const int bm = blockIdx.y * 128;
    const int bn = blockIdx.x * 256;
    const int z  = blockIdx.z;

    const size_t woff = (size_t)z * D_MOD * D_MOD;
    float acc[4][4][4];
    gemm_mainloop(sb, Ahi + (size_t)bm * D_MOD, Alo + (size_t)bm * D_MOD,
                  Whi + woff + (size_t)bn * D_MOD, Wlo + woff + (size_t)bn * D_MOD,
                  tid, wm, wn, lane, acc);

    if (z == 2) {
        const int mrow = bm + wm * 64 + (lane >> 2);
        const int ncol = bn + wn * 32 + (lane & 3) * 2;
#pragma unroll
        for (int mt = 0; mt < 4; mt++)
#pragma unroll
            for (int nt = 0; nt < 4; nt++) {
                uint32_t lo;
                size_t i0 = ((size_t)(mrow + mt * 16)     * D_MOD + ncol + nt * 8) >> 1;
                size_t i1 = ((size_t)(mrow + mt * 16 + 8) * D_MOD + ncol + nt * 8) >> 1;
                vhi[i0] = split2(acc[mt][nt][0], acc[mt][nt][1], lo); vlo[i0] = lo;
                vhi[i1] = split2(acc[mt][nt][2], acc[mt][nt][3], lo); vlo[i1] = lo;
            }
        return;
    }

    // Q/K: stage acc tile (128x256 fp32) in smem, then RoPE + split.
    __syncthreads();
    float* sf = reinterpret_cast<float*>(smem);
    const int r0 = wm * 64 + (lane >> 2);
    const int c0 = wn * 32 + (lane & 3) * 2;
#pragma unroll
    for (int mt = 0; mt < 4; mt++)
#pragma unroll
        for (int nt = 0; nt < 4; nt++) {
            sf[(r0 + mt * 16)     * EPIP + c0 + nt * 8]     = acc[mt][nt][0];
            sf[(r0 + mt * 16)     * EPIP + c0 + nt * 8 + 1] = acc[mt][nt][1];
            sf[(r0 + mt * 16 + 8) * EPIP + c0 + nt * 8]     = acc[mt][nt][2];
            sf[(r0 + mt * 16 + 8) * EPIP + c0 + nt * 8 + 1] = acc[mt][nt][3];
        }
    __syncthreads();

    uint32_t* OH = z ? khi : qhi;
    uint32_t* OL = z ? klo : qlo;
#pragma unroll
    for (int head = 0; head < 2; head++) {
        const int hc = head * 128;
#pragma unroll
        for (int it = 0; it < 8; it++) {
            int idx = tid + it * GTHREADS;     // 0..4095
            int r = idx >> 5;                  // 0..127
            int d = (idx & 31) * 2;            // 0..62
            float2 v1 = *reinterpret_cast<const float2*>(sf + r * EPIP + hc + d);
            float2 v2 = *reinterpret_cast<const float2*>(sf + r * EPIP + hc + 64 + d);
            int gm = bm + r;
            int srow = gm & (S_LEN - 1);
            float2 c1 = *reinterpret_cast<const float2*>(cosb + srow * HD + d);
            float2 s1 = *reinterpret_cast<const float2*>(sinb + srow * HD + d);
            float2 c2 = *reinterpret_cast<const float2*>(cosb + srow * HD + 64 + d);
            float2 s2 = *reinterpret_cast<const float2*>(sinb + srow * HD + 64 + d);
            float o1x = v1.x * c1.x - v2.x * s1.x;
            float o1y = v1.y * c1.y - v2.y * s1.y;
            float o2x = v2.x * c2.x + v1.x * s2.x;
            float o2y = v2.y * c2.y + v1.y * s2.y;
            size_t base = (size_t)gm * D_MOD + bn + hc;
            uint32_t lo;
            OH[(base + d) >> 1]      = split2(o1x, o1y, lo); OL[(base + d) >> 1]      = lo;
            OH[(base + 64 + d) >> 1] = split2(o2x, o2y, lo); OL[(base + 64 + d) >> 1] = lo;
        }
    }
}

// ---------------------------------------------------------------------------
// Flash attention (causal) with HMMA bf16 3-product split. (R11 version)
// ---------------------------------------------------------------------------
#define AP    136
#define APB   (AP * 2)
#define QTILE (128 * APB)
#define KVT   (64 * APB)
#define KVSTG (4 * KVT)
#define SKV0  (2 * QTILE)
#define ATTN_SMEM (2 * QTILE + 2 * KVSTG)   // 208896

__device__ __forceinline__ void attn_g2s_kv(
    uint32_t dst, const __nv_bfloat16* kh, const __nv_bfloat16* kl,
    const __nv_bfloat16* vh, const __nv_bfloat16* vl,
    size_t gbase, int tid)
{
    const __nv_bfloat16* ptrs[4] = {kh, kl, vh, vl};
#pragma unroll
    for (int t = 0; t < 4; t++) {
#pragma unroll
        for (int i = 0; i < 4; i++) {
            int idx = tid + i * 256;
            int r = idx >> 4;
            int c = idx & 15;
            CP_ASYNC16(dst + t * KVT + r * APB + c * 16,
                       ptrs[t] + gbase + (size_t)r * D_MOD + c * 8);
        }
    }
}

__global__ __launch_bounds__(256, 1) void attn_mma(
    const __nv_bfloat16* __restrict__ qh_, const __nv_bfloat16* __restrict__ ql_,
    const __nv_bfloat16* __restrict__ kh_, const __nv_bfloat16* __restrict__ kl_,
    const __nv_bfloat16* __restrict__ vh_, const __nv_bfloat16* __restrict__ vl_,
    uint32_t* __restrict__ aohi, uint32_t* __restrict__ aolo)
{
    extern __shared__ char smem[];
    uint32_t sb = smem_u32(smem);
    const int tid  = threadIdx.x;
    const int wid  = tid >> 5;
    const int lane = tid & 31;
    const int bid = blockIdx.x;
    const int qb = 15 - (bid >> 5);
    const int bh = bid & 31;
    const int b  = bh >> 4;
    const int h  = bh & 15;

    const size_t row0 = (size_t)b * S_LEN;
    const int    hoff = h * HD;
    const int    q0   = qb * 128;

    {
        const size_t qg = (row0 + q0) * D_MOD + hoff;
#pragma unroll
        for (int i = 0; i < 8; i++) {
            int idx = tid + i * 256;
            int r = idx >> 4;
            int c = idx & 15;
            uint32_t d = sb + r * APB + c * 16;
            size_t g = qg + (size_t)r * D_MOD + c * 8;
            CP_ASYNC16(d,         qh_ + g);
            CP_ASYNC16(d + QTILE, ql_ + g);
        }
        attn_g2s_kv(sb + SKV0, kh_, kl_, vh_, vl_, row0 * D_MOD + hoff, tid);
        CP_COMMIT();
    }

    float oacc[16][4];
#pragma unroll
    for (int j = 0; j < 16; j++)
#pragma unroll
        for (int e = 0; e < 4; e++) oacc[j][e] = 0.f;
    float m0 = -1e30f, m1 = -1e30f, l0 = 0.f, l1 = 0.f;

    const float sl2 = 0.08838834764831845f * 1.4426950408889634f;
    const int kb_max = qb * 2 + 1;
    const int rg0 = q0 + wid * 16 + (lane >> 2);
    const int rg1 = rg0 + 8;

    const uint32_t a_off = (uint32_t)((lane & 15) * APB + (lane >> 4) * 16);
    const uint32_t b_off = (uint32_t)(((lane >> 4) * 8 + (lane & 7)) * APB +
                                      ((lane >> 3) & 1) * 16);
    const uint32_t v_off = (uint32_t)(((lane & 7) + ((lane >> 3) & 1) * 8) * APB +
                                      (lane >> 4) * 16);

    for (int kb = 0; kb <= kb_max; kb++) {
        if (kb + 1 <= kb_max) {
            attn_g2s_kv(sb + SKV0 + ((kb + 1) & 1) * KVSTG, kh_, kl_, vh_, vl_,
                        (row0 + (kb + 1) * 64) * D_MOD + hoff, tid);
            CP_COMMIT();
            CP_WAIT1();
        } else {
            CP_WAIT0();
        }
        __syncthreads();

        const uint32_t stg = sb + SKV0 + (kb & 1) * KVSTG;

        float sacc[8][4];
#pragma unroll
        for (int j = 0; j < 8; j++)
#pragma unroll
            for (int e = 0; e < 4; e++) sacc[j][e] = 0.f;

#pragma unroll
        for (int t = 0; t < 8; t++) {
            uint32_t qa = sb + (wid * 16) * APB + t * 32 + a_off;
            uint32_t qhF[4], qlF[4];
            ldm_x4(qa,         qhF[0], qhF[1], qhF[2], qhF[3]);
            ldm_x4(qa + QTILE, qlF[0], qlF[1], qlF[2], qlF[3]);
#pragma unroll
            for (int ng = 0; ng < 4; ng++) {
                uint32_t ka = stg + (ng * 16) * APB + t * 32 + b_off;
                uint32_t khF[4], klF[4];
                ldm_x4(ka,       khF[0], khF[1], khF[2], khF[3]);
                ldm_x4(ka + KVT, klF[0], klF[1], klF[2], klF[3]);
                mma_bf16(sacc[2*ng],   qhF, khF + 0);
                mma_bf16(sacc[2*ng],   qhF, klF + 0);
                mma_bf16(sacc[2*ng],   qlF, khF + 0);
                mma_bf16(sacc[2*ng+1], qhF, khF + 2);
                mma_bf16(sacc[2*ng+1], qhF, klF + 2);
                mma_bf16(sacc[2*ng+1], qlF, khF + 2);
            }
        }

        const bool diag = (kb >= 2 * qb);
        float mx0 = -1e30f, mx1 = -1e30f;
#pragma unroll
        for (int j = 0; j < 8; j++) {
            int colb = kb * 64 + 8 * j + 2 * (lane & 3);
#pragma unroll
            for (int e = 0; e < 4; e++) {
                float v = sacc[j][e] * sl2;
                if (diag) {
                    int col = colb + (e & 1);
                    int row = (e < 2) ? rg0 : rg1;
                    if (col > row) v = -1e30f;
                }
                sacc[j][e] = v;
            }
            mx0 = fmaxf(mx0, fmaxf(sacc[j][0], sacc[j][1]));
            mx1 = fmaxf(mx1, fmaxf(sacc[j][2], sacc[j][3]));
        }
        mx0 = fmaxf(mx0, __shfl_xor_sync(0xffffffffu, mx0, 1));
        mx0 = fmaxf(mx0, __shfl_xor_sync(0xffffffffu, mx0, 2));
        mx1 = fmaxf(mx1, __shfl_xor_sync(0xffffffffu, mx1, 1));
        mx1 = fmaxf(mx1, __shfl_xor_sync(0xffffffffu, mx1, 2));

        float mn0 = fmaxf(m0, mx0), mn1 = fmaxf(m1, mx1);
        float corr0 = ex2f(m0 - mn0), corr1 = ex2f(m1 - mn1);
        m0 = mn0; m1 = mn1;

        float ps0 = 0.f, ps1 = 0.f;
#pragma unroll
        for (int j = 0; j < 8; j++) {
            sacc[j][0] = ex2f(sacc[j][0] - mn0);
            sacc[j][1] = ex2f(sacc[j][1] - mn0);
            sacc[j][2] = ex2f(sacc[j][2] - mn1);
            sacc[j][3] = ex2f(sacc[j][3] - mn1);
            ps0 += sacc[j][0] + sacc[j][1];
            ps1 += sacc[j][2] + sacc[j][3];
        }
        l0 = l0 * corr0 + ps0;
        l1 = l1 * corr1 + ps1;
#pragma unroll
        for (int j = 0; j < 16; j++) {
            oacc[j][0] *= corr0; oacc[j][1] *= corr0;
            oacc[j][2] *= corr1; oacc[j][3] *= corr1;
        }

#pragma unroll
        for (int t = 0; t < 4; t++) {
            uint32_t pah[4], pal[4];
            pah[0] = split2(sacc[2*t][0],   sacc[2*t][1],   pal[0]);
            pah[1] = split2(sacc[2*t][2],   sacc[2*t][3],   pal[1]);
            pah[2] = split2(sacc[2*t+1][0], sacc[2*t+1][1], pal[2]);
            pah[3] = split2(sacc[2*t+1][2], sacc[2*t+1][3], pal[3]);
#pragma unroll
            for (int ng = 0; ng < 8; ng++) {
                uint32_t va = stg + 2 * KVT + (t * 16) * APB + ng * 32 + v_off;
                uint32_t vhF[4], vlF[4];
                ldm_x4t(va,       vhF[0], vhF[1], vhF[2], vhF[3]);
                ldm_x4t(va + KVT, vlF[0], vlF[1], vlF[2], vlF[3]);
                mma_bf16(oacc[2*ng],   pah, vhF + 0);
                mma_bf16(oacc[2*ng],   pah, vlF + 0);
                mma_bf16(oacc[2*ng],   pal, vhF + 0);
                mma_bf16(oacc[2*ng+1], pah, vhF + 2);
                mma_bf16(oacc[2*ng+1], pah, vlF + 2);
                mma_bf16(oacc[2*ng+1], pal, vhF + 2);
            }
        }
        __syncthreads();
    }

    l0 += __shfl_xor_sync(0xffffffffu, l0, 1);
    l0 += __shfl_xor_sync(0xffffffffu, l0, 2);
    l1 += __shfl_xor_sync(0xffffffffu, l1, 1);
    l1 += __shfl_xor_sync(0xffffffffu, l1, 2);
    float inv0 = 1.f / l0, inv1 = 1.f / l1;

    const uint32_t i0 = (uint32_t)(((row0 + rg0) * D_MOD + hoff + 2 * (lane & 3)) >> 1);
    const uint32_t i1 = (uint32_t)(((row0 + rg1) * D_MOD + hoff + 2 * (lane & 3)) >> 1);
#pragma unroll
    for (int j = 0; j < 16; j++) {
        uint32_t lo;
        uint32_t hi = split2(oacc[j][0] * inv0, oacc[j][1] * inv0, lo);
        aohi[i0 + 4 * j] = hi; aolo[i0 + 4 * j] = lo;
        hi = split2(oacc[j][2] * inv1, oacc[j][3] * inv1, lo);
        aohi[i1 + 4 * j] = hi; aolo[i1 + 4 * j] = lo;
    }
}

// ---------------------------------------------------------------------------
extern "C" void kernel_launch(void* const* d_in, const int* in_sizes, int n_in,
                              void* d_out, int out_size)
{
    const float* x    = (const float*)d_in[0];
    const float* cosb = (const float*)d_in[1];
    const float* sinb = (const float*)d_in[2];
    const float* Wq   = (const float*)d_in[3];
    const float* Wk   = (const float*)d_in[4];
    const float* Wv   = (const float*)d_in[5];
    const float* Wo   = (const float*)d_in[6];
    float* out = (float*)d_out;

    __nv_bfloat16 *xhi, *xlo, *whi, *wlo, *aohi, *aolo;
    __nv_bfloat16 *qhi, *qlo, *khi, *klo, *vhi, *vlo;
    cudaGetSymbolAddress((void**)&xhi,  g_xhi);
    cudaGetSymbolAddress((void**)&xlo,  g_xlo);
    cudaGetSymbolAddress((void**)&whi,  g_whi);
    cudaGetSymbolAddress((void**)&wlo,  g_wlo);
    cudaGetSymbolAddress((void**)&aohi, g_aohi);
    cudaGetSymbolAddress((void**)&aolo, g_aolo);
    cudaGetSymbolAddress((void**)&qhi,  g_qhi);
    cudaGetSymbolAddress((void**)&qlo,  g_qlo);
    cudaGetSymbolAddress((void**)&khi,  g_khi);
    cudaGetSymbolAddress((void**)&klo,  g_klo);
    cudaGetSymbolAddress((void**)&vhi,  g_vhi);
    cudaGetSymbolAddress((void**)&vlo,  g_vlo);

    cudaFuncSetAttribute(gemm_hmma,
                         cudaFuncAttributeMaxDynamicSharedMemorySize, GEMM_SMEM);
    cudaFuncSetAttribute(gemm_qkv,
                         cudaFuncAttributeMaxDynamicSharedMemorySize, GEMM_SMEM);
    cudaFuncSetAttribute(attn_mma,
                         cudaFuncAttributeMaxDynamicSharedMemorySize, ATTN_SMEM);

    split_all_kernel<<<6144, 256>>>(
        (const float4*)x, (const float4*)Wq, (const float4*)Wk,
        (const float4*)Wv, (const float4*)Wo,
        (uint2*)xhi, (uint2*)xlo, (uint2*)whi, (uint2*)wlo);

    dim3 qkvgrid(D_MOD / 256, M_TOT / 128, 3);   // (8, 32, 3)
    gemm_qkv<<<qkvgrid, GTHREADS, GEMM_SMEM>>>(xhi, xlo, whi, wlo, cosb, sinb,
        (uint32_t*)qhi, (uint32_t*)qlo, (uint32_t*)khi, (uint32_t*)klo,
        (uint32_t*)vhi, (uint32_t*)vlo);

    attn_mma<<<BATCH * NHEAD * (S_LEN / 128), 256, ATTN_SMEM>>>(
        qhi, qlo, khi, klo, vhi, vlo, (uint32_t*)aohi, (uint32_t*)aolo);

    dim3 ggrid(D_MOD / 256, M_TOT / 128);   // (8, 32)
    gemm_hmma<<<ggrid, GTHREADS, GEMM_SMEM>>>(aohi, aolo,
        whi + 3 * (size_t)D_MOD * D_MOD, wlo + 3 * (size_t)D_MOD * D_MOD, out);
}

// round 17
// speedup vs baseline: 1.0280x; 1.0040x over previous
#include <cuda_runtime.h>
#include <cuda_bf16.h>
#include <math.h>
#include <cstdint>

#define S_LEN   2048
#define D_MOD   2048
#define NHEAD   16
#define HD      128
#define BATCH   2
#define M_TOT   (BATCH * S_LEN)   // 4096

// ---------------------------------------------------------------------------
// helpers
// ---------------------------------------------------------------------------
__device__ __forceinline__ uint32_t smem_u32(const void* p) {
    uint32_t a;
    asm("{ .reg .u64 t; cvta.to.shared.u64 t, %1; cvt.u32.u64 %0, t; }"
        : "=r"(a) : "l"(p));
    return a;
}

#define CP_ASYNC16(dst, src) \
    asm volatile("cp.async.cg.shared.global [%0], [%1], 16;" \
                 :: "r"(dst), "l"(src) : "memory")
#define CP_COMMIT() asm volatile("cp.async.commit_group;" ::: "memory")
#define CP_WAIT1()  asm volatile("cp.async.wait_group 1;" ::: "memory")
#define CP_WAIT0()  asm volatile("cp.async.wait_group 0;" ::: "memory")

__device__ __forceinline__ void ldm_x4(uint32_t addr, uint32_t& r0, uint32_t& r1,
                                       uint32_t& r2, uint32_t& r3) {
    asm volatile("ldmatrix.sync.aligned.m8n8.x4.shared.b16 {%0,%1,%2,%3}, [%4];"
                 : "=r"(r0), "=r"(r1), "=r"(r2), "=r"(r3) : "r"(addr));
}
__device__ __forceinline__ void ldm_x4t(uint32_t addr, uint32_t& r0, uint32_t& r1,
                                        uint32_t& r2, uint32_t& r3) {
    asm volatile("ldmatrix.sync.aligned.m8n8.x4.trans.shared.b16 {%0,%1,%2,%3}, [%4];"
                 : "=r"(r0), "=r"(r1), "=r"(r2), "=r"(r3) : "r"(addr));
}
__device__ __forceinline__ void mma_bf16(float* d, const uint32_t* a, const uint32_t* b) {
    asm volatile(
        "mma.sync.aligned.m16n8k16.row.col.f32.bf16.bf16.f32 "
        "{%0,%1,%2,%3}, {%4,%5,%6,%7}, {%8,%9}, {%0,%1,%2,%3};"
        : "+f"(d[0]), "+f"(d[1]), "+f"(d[2]), "+f"(d[3])
        : "r"(a[0]), "r"(a[1]), "r"(a[2]), "r"(a[3]), "r"(b[0]), "r"(b[1]));
}
__device__ __forceinline__ uint32_t bf16x2_pack(float lo, float hi) {
    uint32_t r;
    asm("cvt.rn.bf16x2.f32 %0, %1, %2;" : "=r"(r) : "f"(hi), "f"(lo));
    return r;
}
__device__ __forceinline__ uint32_t split2(float a, float b, uint32_t& lo) {
    uint32_t h = bf16x2_pack(a, b);
    float ha = __uint_as_float(h << 16);
    float hb = __uint_as_float(h & 0xffff0000u);
    lo = bf16x2_pack(a - ha, b - hb);
    return h;
}
__device__ __forceinline__ float ex2f(float x) {
    float y; asm("ex2.approx.ftz.f32 %0, %1;" : "=f"(y) : "f"(x)); return y;
}

// ---------------------------------------------------------------------------
// Scratch (device globals: allocation-free rule)
// ---------------------------------------------------------------------------
__device__ __nv_bfloat16 g_xhi [M_TOT * D_MOD];
__device__ __nv_bfloat16 g_xlo [M_TOT * D_MOD];
__device__ __nv_bfloat16 g_whi [4][D_MOD * D_MOD];
__device__ __nv_bfloat16 g_wlo [4][D_MOD * D_MOD];
__device__ __nv_bfloat16 g_aohi[M_TOT * D_MOD];
__device__ __nv_bfloat16 g_aolo[M_TOT * D_MOD];
__device__ __nv_bfloat16 g_qhi [M_TOT * D_MOD];
__device__ __nv_bfloat16 g_qlo [M_TOT * D_MOD];
__device__ __nv_bfloat16 g_khi [M_TOT * D_MOD];
__device__ __nv_bfloat16 g_klo [M_TOT * D_MOD];
__device__ __nv_bfloat16 g_vhi [M_TOT * D_MOD];
__device__ __nv_bfloat16 g_vlo [M_TOT * D_MOD];

// ---------------------------------------------------------------------------
// Fused split: x (2 regions) + 4 weights (1 region each) -> hi/lo bf16.
// ---------------------------------------------------------------------------
#define REG4 (1024 * 1024)     // float4 per region
__global__ __launch_bounds__(256) void split_all_kernel(
    const float4* __restrict__ x,
    const float4* __restrict__ w0, const float4* __restrict__ w1,
    const float4* __restrict__ w2, const float4* __restrict__ w3,
    uint2* __restrict__ xhi, uint2* __restrict__ xlo,
    uint2* __restrict__ whi, uint2* __restrict__ wlo)
{
    const int region = blockIdx.x >> 10;
    const int bl     = blockIdx.x & 1023;
    const float4* src; uint2 *ph, *pl;
    switch (region) {
        case 0:  src = x;           ph = xhi;            pl = xlo;            break;
        case 1:  src = x + REG4;    ph = xhi + REG4;     pl = xlo + REG4;     break;
        case 2:  src = w0;          ph = whi;            pl = wlo;            break;
        case 3:  src = w1;          ph = whi + REG4;     pl = wlo + REG4;     break;
        case 4:  src = w2;          ph = whi + 2*REG4;   pl = wlo + 2*REG4;   break;
        default: src = w3;          ph = whi + 3*REG4;   pl = wlo + 3*REG4;   break;
    }
    int base = bl * 256 + threadIdx.x;
    float4 v[4];
#pragma unroll
    for (int t = 0; t < 4; t++)
        v[t] = src[base + t * (REG4 / 4)];
#pragma unroll
    for (int t = 0; t < 4; t++) {
        int i = base + t * (REG4 / 4);
        uint2 hv, lv;
        hv.x = split2(v[t].x, v[t].y, lv.x);
        hv.y = split2(v[t].z, v[t].w, lv.y);
        ph[i] = hv; pl[i] = lv;
    }
}

// ---------------------------------------------------------------------------
// HMMA bf16-split GEMM NT core: C[M,N] = A[M,K] * B[N,K]^T (fp32, 3 products)
// CTA 128x256, BK=64, 512 threads (16 warps, warp tile 64x32), 2-stage pipe.
// ---------------------------------------------------------------------------
#define GTHREADS 512
#define APITCH   144
#define ASZ      (128 * APITCH)
#define BSZ      (256 * APITCH)
#define STAGE_SZ (2 * ASZ + 2 * BSZ)
#define GEMM_SMEM (2 * STAGE_SZ)

__device__ __forceinline__ void g2s_stage(
    uint32_t sbase, const __nv_bfloat16* pAh, const __nv_bfloat16* pAl,
    const __nv_bfloat16* pBh, const __nv_bfloat16* pBl, int kc, int tid)
{
#pragma unroll
    for (int t = 0; t < 2; t++) {
        int idx = tid + t * GTHREADS;
        int row = idx >> 3;
        int c16 = idx & 7;
        uint32_t d = sbase + row * APITCH + c16 * 16;
        size_t g = (size_t)row * D_MOD + kc + c16 * 8;
        CP_ASYNC16(d,       pAh + g);
        CP_ASYNC16(d + ASZ, pAl + g);
    }
#pragma unroll
    for (int t = 0; t < 4; t++) {
        int idx = tid + t * GTHREADS;
        int row = idx >> 3;
        int c16 = idx & 7;
        uint32_t d = sbase + 2 * ASZ + row * APITCH + c16 * 16;
        size_t g = (size_t)row * D_MOD + kc + c16 * 8;
        CP_ASYNC16(d,       pBh + g);
        CP_ASYNC16(d + BSZ, pBl + g);
    }
}

__device__ __forceinline__ void gemm_mainloop(
    uint32_t sb, const __nv_bfloat16* pAh, const __nv_bfloat16* pAl,
    const __nv_bfloat16* pBh, const __nv_bfloat16* pBl,
    int tid, int wm, int wn, int lane, float acc[4][4][4])
{
#pragma unroll
    for (int i = 0; i < 4; i++)
#pragma unroll
        for (int j = 0; j < 4; j++)
#pragma unroll
            for (int e = 0; e < 4; e++) acc[i][j][e] = 0.f;

    const uint32_t a_off = (uint32_t)((lane & 15) * APITCH + (lane >> 4) * 16);
    const uint32_t b_off = (uint32_t)(((lane >> 4) * 8 + (lane & 7)) * APITCH +
                                      ((lane >> 3) & 1) * 16);

    const int nk = D_MOD / 64;
    g2s_stage(sb, pAh, pAl, pBh, pBl, 0, tid);
    CP_COMMIT();

    for (int c = 0; c < nk; c++) {
        const uint32_t stg = sb + (c & 1) * STAGE_SZ;
        CP_WAIT0();
        __syncthreads();

        if (c + 1 < nk) {
            g2s_stage(sb + ((c + 1) & 1) * STAGE_SZ, pAh, pAl, pBh, pBl,
                      (c + 1) * 64, tid);
            CP_COMMIT();
        }

#pragma unroll
        for (int s = 0; s < 4; s++) {
            const uint32_t k0b = s * 32;
            uint32_t ah[4][4], al[4][4];
#pragma unroll
            for (int mt = 0; mt < 4; mt++) {
                uint32_t base = stg + (wm * 64 + mt * 16) * APITCH + k0b + a_off;
                ldm_x4(base,       ah[mt][0], ah[mt][1], ah[mt][2], ah[mt][3]);
                ldm_x4(base + ASZ, al[mt][0], al[mt][1], al[mt][2], al[mt][3]);
            }
            uint32_t bh[4][2], bl[4][2];
#pragma unroll
            for (int ntp = 0; ntp < 2; ntp++) {
                uint32_t base = stg + 2 * ASZ + (wn * 32 + ntp * 16) * APITCH + k0b + b_off;
                ldm_x4(base,       bh[2*ntp][0], bh[2*ntp][1], bh[2*ntp+1][0], bh[2*ntp+1][1]);
                ldm_x4(base + BSZ, bl[2*ntp][0], bl[2*ntp][1], bl[2*ntp+1][0], bl[2*ntp+1][1]);
            }
#pragma unroll
            for (int mt = 0; mt < 4; mt++)
#pragma unroll
                for (int nt = 0; nt < 4; nt++) {
                    mma_bf16(acc[mt][nt], ah[mt], bh[nt]);
                    mma_bf16(acc[mt][nt], ah[mt], bl[nt]);
                    mma_bf16(acc[mt][nt], al[mt], bh[nt]);
                }
        }
    }
}

// Wo GEMM: fp32 output
__global__ __launch_bounds__(GTHREADS, 1) void gemm_hmma(
    const __nv_bfloat16* __restrict__ Ahi, const __nv_bfloat16* __restrict__ Alo,
    const __nv_bfloat16* __restrict__ Bhi, const __nv_bfloat16* __restrict__ Blo,
    float* __restrict__ C)
{
    extern __shared__ char smem[];
    uint32_t sb = smem_u32(smem);
    const int tid  = threadIdx.x;
    const int wid  = tid >> 5;
    const int lane = tid & 31;
    const int wm   = wid & 1;
    const int wn   = wid >> 1;
    const int bm = blockIdx.y * 128;
    const int bn = blockIdx.x * 256;

    float acc[4][4][4];
    gemm_mainloop(sb, Ahi + (size_t)bm * D_MOD, Alo + (size_t)bm * D_MOD,
                  Bhi + (size_t)bn * D_MOD, Blo + (size_t)bn * D_MOD,
                  tid, wm, wn, lane, acc);

    const int mrow = bm + wm * 64 + (lane >> 2);
    const int ncol = bn + wn * 32 + (lane & 3) * 2;
#pragma unroll
    for (int mt = 0; mt < 4; mt++)
#pragma unroll
        for (int nt = 0; nt < 4; nt++) {
            float* c0 = C + (size_t)(mrow + mt * 16)     * D_MOD + ncol + nt * 8;
            float* c1 = C + (size_t)(mrow + mt * 16 + 8) * D_MOD + ncol + nt * 8;
            *reinterpret_cast<float2*>(c0) = make_float2(acc[mt][nt][0], acc[mt][nt][1]);
            *reinterpret_cast<float2*>(c1) = make_float2(acc[mt][nt][2], acc[mt][nt][3]);
        }
}

// Fused QKV GEMM: z selects weight/output. z<2: RoPE+split epilogue, z=2: split.
#define EPIP 264
__global__ __launch_bounds__(GTHREADS, 1) void gemm_qkv(
    const __nv_bfloat16* __restrict__ Ahi, const __nv_bfloat16* __restrict__ Alo,
    const __nv_bfloat16* __restrict__ Whi, const __nv_bfloat16* __restrict__ Wlo,
    const float* __restrict__ cosb, const float* __restrict__ sinb,
    uint32_t* __restrict__ qhi, uint32_t* __restrict__ qlo,
    uint32_t* __restrict__ khi, uint32_t* __restrict__ klo,
    uint32_t* __restrict__ vhi, uint32_t* __restrict__ vlo)
{
    extern __shared__ char smem[];
    uint32_t sb = smem_u32(smem);
    const int tid  = threadIdx.x;
    const int wid  = tid >> 5;
    const int lane = tid & 31;
    const int wm   = wid & 1;
    const int wn   = wid >> 1;
    const int bm = blockIdx.y * 128;
    const int bn = blockIdx.x * 256;
    const int z  = blockIdx.z;

    const size_t woff = (size_t)z * D_MOD * D_MOD;
    float acc[4][4][4];
    gemm_mainloop(sb, Ahi + (size_t)bm * D_MOD, Alo + (size_t)bm * D_MOD,
                  Whi + woff + (size_t)bn * D_MOD, Wlo + woff + (size_t)bn * D_MOD,
                  tid, wm, wn, lane, acc);

    if (z == 2) {
        const int mrow = bm + wm * 64 + (lane >> 2);
        const int ncol = bn + wn * 32 + (lane & 3) * 2;
#pragma unroll
        for (int mt = 0; mt < 4; mt++)
#pragma unroll
            for (int nt = 0; nt < 4; nt++) {
                uint32_t lo;
                size_t i0 = ((size_t)(mrow + mt * 16)     * D_MOD + ncol + nt * 8) >> 1;
                size_t i1 = ((size_t)(mrow + mt * 16 + 8) * D_MOD + ncol + nt * 8) >> 1;
                vhi[i0] = split2(acc[mt][nt][0], acc[mt][nt][1], lo); vlo[i0] = lo;
                vhi[i1] = split2(acc[mt][nt][2], acc[mt][nt][3], lo); vlo[i1] = lo;
            }
        return;
    }

    __syncthreads();
    float* sf = reinterpret_cast<float*>(smem);
    const int r0 = wm * 64 + (lane >> 2);
    const int c0 = wn * 32 + (lane & 3) * 2;
#pragma unroll
    for (int mt = 0; mt < 4; mt++)
#pragma unroll
        for (int nt = 0; nt < 4; nt++) {
            sf[(r0 + mt * 16)     * EPIP + c0 + nt * 8]     = acc[mt][nt][0];
            sf[(r0 + mt * 16)     * EPIP + c0 + nt * 8 + 1] = acc[mt][nt][1];
            sf[(r0 + mt * 16 + 8) * EPIP + c0 + nt * 8]     = acc[mt][nt][2];
            sf[(r0 + mt * 16 + 8) * EPIP + c0 + nt * 8 + 1] = acc[mt][nt][3];
        }
    __syncthreads();

    uint32_t* OH = z ? khi : qhi;
    uint32_t* OL = z ? klo : qlo;
#pragma unroll
    for (int head = 0; head < 2; head++) {
        const int hc = head * 128;
#pragma unroll
        for (int it = 0; it < 8; it++) {
            int idx = tid + it * GTHREADS;
            int r = idx >> 5;
            int d = (idx & 31) * 2;
            float2 v1 = *reinterpret_cast<const float2*>(sf + r * EPIP + hc + d);
            float2 v2 = *reinterpret_cast<const float2*>(sf + r * EPIP + hc + 64 + d);
            int gm = bm + r;
            int srow = gm & (S_LEN - 1);
            float2 c1 = *reinterpret_cast<const float2*>(cosb + srow * HD + d);
            float2 s1 = *reinterpret_cast<const float2*>(sinb + srow * HD + d);
            float2 c2 = *reinterpret_cast<const float2*>(cosb + srow * HD + 64 + d);
            float2 s2 = *reinterpret_cast<const float2*>(sinb + srow * HD + 64 + d);
            float o1x = v1.x * c1.x - v2.x * s1.x;
            float o1y = v1.y * c1.y - v2.y * s1.y;
            float o2x = v2.x * c2.x + v1.x * s2.x;
            float o2y = v2.y * c2.y + v1.y * s2.y;
            size_t base = (size_t)gm * D_MOD + bn + hc;
            uint32_t lo;
            OH[(base + d) >> 1]      = split2(o1x, o1y, lo); OL[(base + d) >> 1]      = lo;
            OH[(base + 64 + d) >> 1] = split2(o2x, o2y, lo); OL[(base + 64 + d) >> 1] = lo;
        }
    }
}

// ---------------------------------------------------------------------------
// Flash attention (causal) with HMMA bf16 3-product split.
// Warps with fully-masked rows skip compute on the upper diagonal block.
// ---------------------------------------------------------------------------
#define AP    136
#define APB   (AP * 2)
#define QTILE (128 * APB)
#define KVT   (64 * APB)
#define KVSTG (4 * KVT)
#define SKV0  (2 * QTILE)
#define ATTN_SMEM (2 * QTILE + 2 * KVSTG)

__device__ __forceinline__ void attn_g2s_kv(
    uint32_t dst, const __nv_bfloat16* kh, const __nv_bfloat16* kl,
    const __nv_bfloat16* vh, const __nv_bfloat16* vl,
    size_t gbase, int tid)
{
    const __nv_bfloat16* ptrs[4] = {kh, kl, vh, vl};
#pragma unroll
    for (int t = 0; t < 4; t++) {
#pragma unroll
        for (int i = 0; i < 4; i++) {
            int idx = tid + i * 256;
            int r = idx >> 4;
            int c = idx & 15;
            CP_ASYNC16(dst + t * KVT + r * APB + c * 16,
                       ptrs[t] + gbase + (size_t)r * D_MOD + c * 8);
        }
    }
}

__global__ __launch_bounds__(256, 1) void attn_mma(
    const __nv_bfloat16* __restrict__ qh_, const __nv_bfloat16* __restrict__ ql_,
    const __nv_bfloat16* __restrict__ kh_, const __nv_bfloat16* __restrict__ kl_,
    const __nv_bfloat16* __restrict__ vh_, const __nv_bfloat16* __restrict__ vl_,
    uint32_t* __restrict__ aohi, uint32_t* __restrict__ aolo)
{
    extern __shared__ char smem[];
    uint32_t sb = smem_u32(smem);
    const int tid  = threadIdx.x;
    const int wid  = tid >> 5;
    const int lane = tid & 31;
    const int bid = blockIdx.x;
    const int qb = 15 - (bid >> 5);
    const int bh = bid & 31;
    const int b  = bh >> 4;
    const int h  = bh & 15;

    const size_t row0 = (size_t)b * S_LEN;
    const int    hoff = h * HD;
    const int    q0   = qb * 128;

    {
        const size_t qg = (row0 + q0) * D_MOD + hoff;
#pragma unroll
        for (int i = 0; i < 8; i++) {
            int idx = tid + i * 256;
            int r = idx >> 4;
            int c = idx & 15;
            uint32_t d = sb + r * APB + c * 16;
            size_t g = qg + (size_t)r * D_MOD + c * 8;
            CP_ASYNC16(d,         qh_ + g);
            CP_ASYNC16(d + QTILE, ql_ + g);
        }
        attn_g2s_kv(sb + SKV0, kh_, kl_, vh_, vl_, row0 * D_MOD + hoff, tid);
        CP_COMMIT();
    }

    float oacc[16][4];
#pragma unroll
    for (int j = 0; j < 16; j++)
#pragma unroll
        for (int e = 0; e < 4; e++) oacc[j][e] = 0.f;
    float m0 = -1e30f, m1 = -1e30f, l0 = 0.f, l1 = 0.f;

    const float sl2 = 0.08838834764831845f * 1.4426950408889634f;
    const int kb_max = qb * 2 + 1;
    const int rg0 = q0 + wid * 16 + (lane >> 2);
    const int rg1 = rg0 + 8;

    const uint32_t a_off = (uint32_t)((lane & 15) * APB + (lane >> 4) * 16);
    const uint32_t b_off = (uint32_t)(((lane >> 4) * 8 + (lane & 7)) * APB +
                                      ((lane >> 3) & 1) * 16);
    const uint32_t v_off = (uint32_t)(((lane & 7) + ((lane >> 3) & 1) * 8) * APB +
                                      (lane >> 4) * 16);

    for (int kb = 0; kb <= kb_max; kb++) {
        if (kb + 1 <= kb_max) {
            attn_g2s_kv(sb + SKV0 + ((kb + 1) & 1) * KVSTG, kh_, kl_, vh_, vl_,
                        (row0 + (kb + 1) * 64) * D_MOD + hoff, tid);
            CP_COMMIT();
            CP_WAIT1();
        } else {
            CP_WAIT0();
        }
        __syncthreads();

        // upper diagonal block: warps 0-3 cover rows < all columns -> fully
        // masked -> P == 0 -> zero contribution. Skip their compute entirely
        // (state m/l/oacc unchanged; barriers below still executed by all).
        const bool fully_masked = (kb == 2 * qb + 1) && (wid < 4);
        if (!fully_masked) {
            const uint32_t stg = sb + SKV0 + (kb & 1) * KVSTG;

            float sacc[8][4];
#pragma unroll
            for (int j = 0; j < 8; j++)
#pragma unroll
                for (int e = 0; e < 4; e++) sacc[j][e] = 0.f;

#pragma unroll
            for (int t = 0; t < 8; t++) {
                uint32_t qa = sb + (wid * 16) * APB + t * 32 + a_off;
                uint32_t qhF[4], qlF[4];
                ldm_x4(qa,         qhF[0], qhF[1], qhF[2], qhF[3]);
                ldm_x4(qa + QTILE, qlF[0], qlF[1], qlF[2], qlF[3]);
#pragma unroll
                for (int ng = 0; ng < 4; ng++) {
                    uint32_t ka = stg + (ng * 16) * APB + t * 32 + b_off;
                    uint32_t khF[4], klF[4];
                    ldm_x4(ka,       khF[0], khF[1], khF[2], khF[3]);
                    ldm_x4(ka + KVT, klF[0], klF[1], klF[2], klF[3]);
                    mma_bf16(sacc[2*ng],   qhF, khF + 0);
                    mma_bf16(sacc[2*ng],   qhF, klF + 0);
                    mma_bf16(sacc[2*ng],   qlF, khF + 0);
                    mma_bf16(sacc[2*ng+1], qhF, khF + 2);
                    mma_bf16(sacc[2*ng+1], qhF, klF + 2);
                    mma_bf16(sacc[2*ng+1], qlF, khF + 2);
                }
            }

            const bool diag = (kb >= 2 * qb);
            float mx0 = -1e30f, mx1 = -1e30f;
#pragma unroll
            for (int j = 0; j < 8; j++) {
                int colb = kb * 64 + 8 * j + 2 * (lane & 3);
#pragma unroll
                for (int e = 0; e < 4; e++) {
                    float v = sacc[j][e] * sl2;
                    if (diag) {
                        int col = colb + (e & 1);
                        int row = (e < 2) ? rg0 : rg1;
                        if (col > row) v = -1e30f;
                    }
                    sacc[j][e] = v;
                }
                mx0 = fmaxf(mx0, fmaxf(sacc[j][0], sacc[j][1]));
                mx1 = fmaxf(mx1, fmaxf(sacc[j][2], sacc[j][3]));
            }
            mx0 = fmaxf(mx0, __shfl_xor_sync(0xffffffffu, mx0, 1));
            mx0 = fmaxf(mx0, __shfl_xor_sync(0xffffffffu, mx0, 2));
            mx1 = fmaxf(mx1, __shfl_xor_sync(0xffffffffu, mx1, 1));
            mx1 = fmaxf(mx1, __shfl_xor_sync(0xffffffffu, mx1, 2));

            float mn0 = fmaxf(m0, mx0), mn1 = fmaxf(m1, mx1);
            float corr0 = ex2f(m0 - mn0), corr1 = ex2f(m1 - mn1);
            m0 = mn0; m1 = mn1;

            float ps0 = 0.f, ps1 = 0.f;
#pragma unroll
            for (int j = 0; j < 8; j++) {
                sacc[j][0] = ex2f(sacc[j][0] - mn0);
                sacc[j][1] = ex2f(sacc[j][1] - mn0);
                sacc[j][2] = ex2f(sacc[j][2] - mn1);
                sacc[j][3] = ex2f(sacc[j][3] - mn1);
                ps0 += sacc[j][0] + sacc[j][1];
                ps1 += sacc[j][2] + sacc[j][3];
            }
            l0 = l0 * corr0 + ps0;
            l1 = l1 * corr1 + ps1;
#pragma unroll
            for (int j = 0; j < 16; j++) {
                oacc[j][0] *= corr0; oacc[j][1] *= corr0;
                oacc[j][2] *= corr1; oacc[j][3] *= corr1;
            }

#pragma unroll
            for (int t = 0; t < 4; t++) {
                uint32_t pah[4], pal[4];
                pah[0] = split2(sacc[2*t][0],   sacc[2*t][1],   pal[0]);
                pah[1] = split2(sacc[2*t][2],   sacc[2*t][3],   pal[1]);
                pah[2] = split2(sacc[2*t+1][0], sacc[2*t+1][1], pal[2]);
                pah[3] = split2(sacc[2*t+1][2], sacc[2*t+1][3], pal[3]);
#pragma unroll
                for (int ng = 0; ng < 8; ng++) {
                    uint32_t va = stg + 2 * KVT + (t * 16) * APB + ng * 32 + v_off;
                    uint32_t vhF[4], vlF[4];
                    ldm_x4t(va,       vhF[0], vhF[1], vhF[2], vhF[3]);
                    ldm_x4t(va + KVT, vlF[0], vlF[1], vlF[2], vlF[3]);
                    mma_bf16(oacc[2*ng],   pah, vhF + 0);
                    mma_bf16(oacc[2*ng],   pah, vlF + 0);
                    mma_bf16(oacc[2*ng],   pal, vhF + 0);
                    mma_bf16(oacc[2*ng+1], pah, vhF + 2);
                    mma_bf16(oacc[2*ng+1], pah, vlF + 2);
                    mma_bf16(oacc[2*ng+1], pal, vhF + 2);
                }
            }
        }
        __syncthreads();
    }

    l0 += __shfl_xor_sync(0xffffffffu, l0, 1);
    l0 += __shfl_xor_sync(0xffffffffu, l0, 2);
    l1 += __shfl_xor_sync(0xffffffffu, l1, 1);
    l1 += __shfl_xor_sync(0xffffffffu, l1, 2);
    float inv0 = 1.f / l0, inv1 = 1.f / l1;

    const uint32_t i0 = (uint32_t)(((row0 + rg0) * D_MOD + hoff + 2 * (lane & 3)) >> 1);
    const uint32_t i1 = (uint32_t)(((row0 + rg1) * D_MOD + hoff + 2 * (lane & 3)) >> 1);
#pragma unroll
    for (int j = 0; j < 16; j++) {
        uint32_t lo;
        uint32_t hi = split2(oacc[j][0] * inv0, oacc[j][1] * inv0, lo);
        aohi[i0 + 4 * j] = hi; aolo[i0 + 4 * j] = lo;
        hi = split2(oacc[j][2] * inv1, oacc[j][3] * inv1, lo);
        aohi[i1 + 4 * j] = hi; aolo[i1 + 4 * j] = lo;
    }
}

// ---------------------------------------------------------------------------
extern "C" void kernel_launch(void* const* d_in, const int* in_sizes, int n_in,
                              void* d_out, int out_size)
{
    const float* x    = (const float*)d_in[0];
    const float* cosb = (const float*)d_in[1];
    const float* sinb = (const float*)d_in[2];
    const float* Wq   = (const float*)d_in[3];
    const float* Wk   = (const float*)d_in[4];
    const float* Wv   = (const float*)d_in[5];
    const float* Wo   = (const float*)d_in[6];
    float* out = (float*)d_out;

    __nv_bfloat16 *xhi, *xlo, *whi, *wlo, *aohi, *aolo;
    __nv_bfloat16 *qhi, *qlo, *khi, *klo, *vhi, *vlo;
    cudaGetSymbolAddress((void**)&xhi,  g_xhi);
    cudaGetSymbolAddress((void**)&xlo,  g_xlo);
    cudaGetSymbolAddress((void**)&whi,  g_whi);
    cudaGetSymbolAddress((void**)&wlo,  g_wlo);
    cudaGetSymbolAddress((void**)&aohi, g_aohi);
    cudaGetSymbolAddress((void**)&aolo, g_aolo);
    cudaGetSymbolAddress((void**)&qhi,  g_qhi);
    cudaGetSymbolAddress((void**)&qlo,  g_qlo);
    cudaGetSymbolAddress((void**)&khi,  g_khi);
    cudaGetSymbolAddress((void**)&klo,  g_klo);
    cudaGetSymbolAddress((void**)&vhi,  g_vhi);
    cudaGetSymbolAddress((void**)&vlo,  g_vlo);

    cudaFuncSetAttribute(gemm_hmma,
                         cudaFuncAttributeMaxDynamicSharedMemorySize, GEMM_SMEM);
    cudaFuncSetAttribute(gemm_qkv,
                         cudaFuncAttributeMaxDynamicSharedMemorySize, GEMM_SMEM);
    cudaFuncSetAttribute(attn_mma,
                         cudaFuncAttributeMaxDynamicSharedMemorySize, ATTN_SMEM);

    split_all_kernel<<<6144, 256>>>(
        (const float4*)x, (const float4*)Wq, (const float4*)Wk,
        (const float4*)Wv, (const float4*)Wo,
        (uint2*)xhi, (uint2*)xlo, (uint2*)whi, (uint2*)wlo);

    dim3 qkvgrid(D_MOD / 256, M_TOT / 128, 3);   // (8, 32, 3)
    gemm_qkv<<<qkvgrid, GTHREADS, GEMM_SMEM>>>(xhi, xlo, whi, wlo, cosb, sinb,
        (uint32_t*)qhi, (uint32_t*)qlo, (uint32_t*)khi, (uint32_t*)klo,
        (uint32_t*)vhi, (uint32_t*)vlo);

    attn_mma<<<BATCH * NHEAD * (S_LEN / 128), 256, ATTN_SMEM>>>(
        qhi, qlo, khi, klo, vhi, vlo, (uint32_t*)aohi, (uint32_t*)aolo);

    dim3 ggrid(D_MOD / 256, M_TOT / 128);   // (8, 32)
    gemm_hmma<<<ggrid, GTHREADS, GEMM_SMEM>>>(aohi, aolo,
        whi + 3 * (size_t)D_MOD * D_MOD, wlo + 3 * (size_t)D_MOD * D_MOD, out);
}